// round 2
// baseline (speedup 1.0000x reference)
#include <cuda_runtime.h>
#include <cuda_bf16.h>
#include <math.h>

#define BB 32
#define SS 512
#define HH 768
#define EE 4096
#define NH 8
#define DHD 96
#define NEGV -1000000000.0f
#define CAPN 256
#define CAPD 64

// ------------- scratch ------------------------------------------------------
__device__ float g_xl[BB * SS * HH];
__device__ float g_xr[BB * SS * HH];
__device__ float g_msgg[BB * SS * HH];
__device__ int   g_cnt[BB * SS];
__device__ int   g_off[BB * SS];
__device__ int   g_cur[BB * SS];
__device__ int   g_esrc[BB * EE];
__device__ float g_dxl[BB * CAPD * HH];
__device__ float g_diffg0[BB * HH];
__device__ float g_r[BB * NH * HH];
__device__ float g_attn[BB * NH * SS];
__device__ float g_u[BB * NH * HH];

__global__ void zero_kernel() {
    int i = blockIdx.x * 256 + threadIdx.x;
    if (i < BB * SS) g_cnt[i] = 0;
    if (i < BB * NH * HH) g_u[i] = 0.f;
}

// ------------- big GEMM: C = A[M,K] @ W[K,N] + bias -------------------------
__global__ __launch_bounds__(256) void gemm_bias_kernel(
    const float* __restrict__ A, const float* __restrict__ W,
    const float* __restrict__ bias, int which, int M, int N, int K)
{
    float* C = which ? g_xr : g_xl;
    __shared__ float As[16][132];
    __shared__ float Bs[16][68];
    int tid = threadIdx.x;
    int bm = blockIdx.y * 128, bn = blockIdx.x * 64;
    int ar = tid >> 2, ac = (tid & 3) << 2;
    int brr = tid >> 4, bcc = (tid & 15) << 2;
    int ty = tid >> 4, tx = tid & 15;
    float acc[8][4];
#pragma unroll
    for (int i = 0; i < 8; i++)
#pragma unroll
        for (int j = 0; j < 4; j++) acc[i][j] = 0.f;

    for (int kt = 0; kt < K; kt += 16) {
        float4 a0 = *(const float4*)(A + (size_t)(bm + ar) * K + kt + ac);
        float4 a1 = *(const float4*)(A + (size_t)(bm + ar + 64) * K + kt + ac);
        As[ac + 0][ar] = a0.x; As[ac + 1][ar] = a0.y;
        As[ac + 2][ar] = a0.z; As[ac + 3][ar] = a0.w;
        As[ac + 0][ar + 64] = a1.x; As[ac + 1][ar + 64] = a1.y;
        As[ac + 2][ar + 64] = a1.z; As[ac + 3][ar + 64] = a1.w;
        *(float4*)&Bs[brr][bcc] = *(const float4*)(W + (size_t)(kt + brr) * N + bn + bcc);
        __syncthreads();
#pragma unroll
        for (int k = 0; k < 16; k++) {
            float4 aA = *(float4*)&As[k][ty << 3];
            float4 aB = *(float4*)&As[k][(ty << 3) + 4];
            float4 b4 = *(float4*)&Bs[k][tx << 2];
            float ra[8] = {aA.x, aA.y, aA.z, aA.w, aB.x, aB.y, aB.z, aB.w};
#pragma unroll
            for (int i = 0; i < 8; i++) {
                acc[i][0] = fmaf(ra[i], b4.x, acc[i][0]);
                acc[i][1] = fmaf(ra[i], b4.y, acc[i][1]);
                acc[i][2] = fmaf(ra[i], b4.z, acc[i][2]);
                acc[i][3] = fmaf(ra[i], b4.w, acc[i][3]);
            }
        }
        __syncthreads();
    }
    float4 bv4 = *(const float4*)(bias + bn + (tx << 2));
#pragma unroll
    for (int i = 0; i < 8; i++) {
        float4 o;
        o.x = acc[i][0] + bv4.x; o.y = acc[i][1] + bv4.y;
        o.z = acc[i][2] + bv4.z; o.w = acc[i][3] + bv4.w;
        *(float4*)(C + (size_t)(bm + (ty << 3) + i) * N + bn + (tx << 2)) = o;
    }
}

// ------------- CSR build ----------------------------------------------------
__global__ void count_kernel(const int* __restrict__ ei) {
    int idx = blockIdx.x * 256 + threadIdx.x;
    if (idx >= BB * EE) return;
    int b = idx >> 12, e = idx & 4095;
    int s = ei[b * 2 * EE + e], d = ei[b * 2 * EE + EE + e];
    if ((unsigned)s < SS && (unsigned)d < SS) atomicAdd(&g_cnt[b * SS + d], 1);
}

__global__ void scan_kernel() {
    int b = blockIdx.x, tid = threadIdx.x;
    __shared__ int sc[SS];
    int c = g_cnt[b * SS + tid];
    sc[tid] = c;
    __syncthreads();
    for (int off = 1; off < SS; off <<= 1) {
        int t = (tid >= off) ? sc[tid - off] : 0;
        __syncthreads();
        sc[tid] += t;
        __syncthreads();
    }
    int ex = sc[tid] - c;
    g_off[b * SS + tid] = ex;
    g_cur[b * SS + tid] = ex;
}

__global__ void scatter_kernel(const int* __restrict__ ei) {
    int idx = blockIdx.x * 256 + threadIdx.x;
    if (idx >= BB * EE) return;
    int b = idx >> 12, e = idx & 4095;
    int s = ei[b * 2 * EE + e], d = ei[b * 2 * EE + EE + e];
    if ((unsigned)s < SS && (unsigned)d < SS) {
        int p = atomicAdd(&g_cur[b * SS + d], 1);
        g_esrc[b * EE + p] = s;
    }
}

// ------------- msg GAT per destination node ---------------------------------
__global__ __launch_bounds__(128) void gat_node_kernel(
    const float* __restrict__ att, const float* __restrict__ gbias,
    const float* __restrict__ msg)
{
    int n = blockIdx.x, b = blockIdx.y;
    int tid = threadIdx.x;
    int node = b * SS + n;
    __shared__ float xr_s[HH], att_s[HH];
    __shared__ float ev[CAPN];
    __shared__ int srcs[CAPN];
    __shared__ float red[128];
    for (int h = tid; h < HH; h += 128) {
        xr_s[h]  = g_xr[(size_t)node * HH + h];
        att_s[h] = att[h];
    }
    int deg = g_cnt[node]; if (deg > CAPN - 1) deg = CAPN - 1;
    int base = g_off[node];
    for (int i = tid; i < deg; i += 128) srcs[i] = g_esrc[b * EE + base + i];
    if (tid == 0) srcs[deg] = n;
    __syncthreads();
    int d = deg + 1;

    int warp = tid >> 5, lane = tid & 31;
    for (int i = warp; i < d; i += 4) {
        const float* xlr = g_xl + (size_t)(b * SS + srcs[i]) * HH;
        float s = 0.f;
        for (int h = lane; h < HH; h += 32) {
            float z = xlr[h] + xr_s[h];
            z = z > 0.f ? z : 0.2f * z;
            s = fmaf(z, att_s[h], s);
        }
#pragma unroll
        for (int o = 16; o; o >>= 1) s += __shfl_xor_sync(0xffffffffu, s, o);
        if (lane == 0) ev[i] = s;
    }
    __syncthreads();

    float m = -3.4e38f;
    for (int i = tid; i < d; i += 128) m = fmaxf(m, ev[i]);
    red[tid] = m; __syncthreads();
    for (int o = 64; o; o >>= 1) { if (tid < o) red[tid] = fmaxf(red[tid], red[tid + o]); __syncthreads(); }
    float emax = red[0]; __syncthreads();
    float ssum = 0.f;
    for (int i = tid; i < d; i += 128) { float p = expf(ev[i] - emax); ev[i] = p; ssum += p; }
    red[tid] = ssum; __syncthreads();
    for (int o = 64; o; o >>= 1) { if (tid < o) red[tid] += red[tid + o]; __syncthreads(); }
    float inv = 1.f / red[0];
    __syncthreads();

    for (int h = tid; h < HH; h += 128) {
        float a = 0.f;
        for (int i = 0; i < d; i++)
            a = fmaf(ev[i], g_xl[(size_t)(b * SS + srcs[i]) * HH + h], a);
        g_msgg[(size_t)node * HH + h] = a * inv + gbias[h] + msg[(size_t)node * HH + h];
    }
}

// ------------- diff GAT at node 0 only (per batch) --------------------------
__global__ __launch_bounds__(256) void diff0_kernel(
    const float* __restrict__ diff, const int* __restrict__ ei,
    const float* __restrict__ wl, const float* __restrict__ bl,
    const float* __restrict__ wr, const float* __restrict__ br,
    const float* __restrict__ att, const float* __restrict__ gbias)
{
    int b = blockIdx.x, tid = threadIdx.x;
    __shared__ float xrows[8][HH];
    __shared__ float xr0[HH], x0s[HH];
    __shared__ float evals[CAPD];
    __shared__ int srcs[CAPD];
    __shared__ float red[256];
    __shared__ int scnt;
    if (tid == 0) scnt = 0;
    const float* x0 = diff + (size_t)b * SS * HH;
    for (int j = tid; j < HH; j += 256) x0s[j] = x0[j];
    __syncthreads();
    int j0 = tid, j1 = tid + 256, j2 = tid + 512;
    {   // xr0 = x0 @ wr + br
        float a0 = br[j0], a1 = br[j1], a2 = br[j2];
        for (int i = 0; i < HH; i++) {
            float x = x0s[i]; const float* w = wr + (size_t)i * HH;
            a0 = fmaf(x, w[j0], a0); a1 = fmaf(x, w[j1], a1); a2 = fmaf(x, w[j2], a2);
        }
        xr0[j0] = a0; xr0[j1] = a1; xr0[j2] = a2;
    }
    for (int e = tid; e < EE; e += 256) {
        int s = ei[b * 2 * EE + e], dd = ei[b * 2 * EE + EE + e];
        if ((unsigned)s < SS && dd == 0) {
            int p = atomicAdd(&scnt, 1);
            if (p < CAPD - 1) srcs[p] = s;
        }
    }
    __syncthreads();
    int nd = min(scnt, CAPD - 1);
    if (tid == 0) srcs[nd] = 0;
    __syncthreads();
    int d = nd + 1;

    for (int c0 = 0; c0 < d; c0 += 8) {
        int nc = min(8, d - c0);
        for (int t = tid; t < nc * HH; t += 256) {
            int s = t / HH, j = t - s * HH;
            xrows[s][j] = diff[((size_t)b * SS + srcs[c0 + s]) * HH + j];
        }
        __syncthreads();
        float acc[8][3];
#pragma unroll
        for (int s = 0; s < 8; s++) { acc[s][0] = bl[j0]; acc[s][1] = bl[j1]; acc[s][2] = bl[j2]; }
        for (int i = 0; i < HH; i++) {
            const float* w = wl + (size_t)i * HH;
            float w0 = w[j0], w1 = w[j1], w2 = w[j2];
#pragma unroll
            for (int s = 0; s < 8; s++) {
                float x = xrows[s][i];
                acc[s][0] = fmaf(x, w0, acc[s][0]);
                acc[s][1] = fmaf(x, w1, acc[s][1]);
                acc[s][2] = fmaf(x, w2, acc[s][2]);
            }
        }
        for (int s = 0; s < nc; s++) {
            float* xp = g_dxl + ((size_t)b * CAPD + c0 + s) * HH;
            xp[j0] = acc[s][0]; xp[j1] = acc[s][1]; xp[j2] = acc[s][2];
            float z0 = acc[s][0] + xr0[j0]; z0 = z0 > 0.f ? z0 : 0.2f * z0;
            float z1 = acc[s][1] + xr0[j1]; z1 = z1 > 0.f ? z1 : 0.2f * z1;
            float z2 = acc[s][2] + xr0[j2]; z2 = z2 > 0.f ? z2 : 0.2f * z2;
            red[tid] = z0 * att[j0] + z1 * att[j1] + z2 * att[j2];
            __syncthreads();
            for (int o = 128; o; o >>= 1) { if (tid < o) red[tid] += red[tid + o]; __syncthreads(); }
            if (tid == 0) evals[c0 + s] = red[0];
            __syncthreads();
        }
    }
    float m = -3.4e38f;
    for (int i = tid; i < d; i += 256) m = fmaxf(m, evals[i]);
    red[tid] = m; __syncthreads();
    for (int o = 128; o; o >>= 1) { if (tid < o) red[tid] = fmaxf(red[tid], red[tid + o]); __syncthreads(); }
    float emax = red[0]; __syncthreads();
    float ssum = 0.f;
    for (int i = tid; i < d; i += 256) { float p = expf(evals[i] - emax); evals[i] = p; ssum += p; }
    red[tid] = ssum; __syncthreads();
    for (int o = 128; o; o >>= 1) { if (tid < o) red[tid] += red[tid + o]; __syncthreads(); }
    float inv = 1.f / red[0];
    __syncthreads();
    float o0 = 0.f, o1 = 0.f, o2 = 0.f;
    for (int s = 0; s < d; s++) {
        const float* xp = g_dxl + ((size_t)b * CAPD + s) * HH;
        float al = evals[s] * inv;
        o0 = fmaf(al, xp[j0], o0);
        o1 = fmaf(al, xp[j1], o1);
        o2 = fmaf(al, xp[j2], o2);
    }
    g_diffg0[b * HH + j0] = o0 + gbias[j0] + x0s[j0];
    g_diffg0[b * HH + j1] = o1 + gbias[j1] + x0s[j1];
    g_diffg0[b * HH + j2] = o2 + gbias[j2] + x0s[j2];
}

// ------------- q0 and folded r ----------------------------------------------
__global__ __launch_bounds__(256) void qr_kernel(
    const float* __restrict__ wq, const float* __restrict__ bq,
    const float* __restrict__ wk)
{
    int b = blockIdx.x, tid = threadIdx.x;
    __shared__ float x[HH], q0[HH];
    for (int j = tid; j < HH; j += 256) x[j] = g_diffg0[b * HH + j];
    __syncthreads();
    int j0 = tid, j1 = tid + 256, j2 = tid + 512;
    {
        float a0 = bq[j0], a1 = bq[j1], a2 = bq[j2];
        for (int i = 0; i < HH; i++) {
            float xv = x[i]; const float* w = wq + (size_t)i * HH;
            a0 = fmaf(xv, w[j0], a0); a1 = fmaf(xv, w[j1], a1); a2 = fmaf(xv, w[j2], a2);
        }
        q0[j0] = a0; q0[j1] = a1; q0[j2] = a2;
    }
    __syncthreads();
    const float RS = 0.10206207261596577f;  // 1/sqrt(96)
    for (int t = tid; t < NH * HH; t += 256) {
        int h = t / HH, i = t - h * HH;
        const float4* wp = (const float4*)(wk + (size_t)i * HH + h * DHD);
        const float4* qp = (const float4*)(q0 + h * DHD);
        float s = 0.f;
#pragma unroll
        for (int d4 = 0; d4 < DHD / 4; d4++) {
            float4 w4 = wp[d4]; float4 q4 = qp[d4];
            s = fmaf(w4.x, q4.x, s); s = fmaf(w4.y, q4.y, s);
            s = fmaf(w4.z, q4.z, s); s = fmaf(w4.w, q4.w, s);
        }
        g_r[(b * NH + h) * HH + i] = s * RS;
    }
}

// ------------- scores -------------------------------------------------------
__global__ __launch_bounds__(256) void scores_kernel(const int* __restrict__ mask) {
    int s = blockIdx.x, b = blockIdx.y, tid = threadIdx.x;
    __shared__ float row[HH];
    for (int j = tid; j < HH; j += 256) row[j] = g_msgg[(size_t)(b * SS + s) * HH + j];
    __syncthreads();
    int warp = tid >> 5, lane = tid & 31;   // warp == head
    const float* rp = g_r + (size_t)(b * NH + warp) * HH;
    float acc = 0.f;
    for (int j = lane; j < HH; j += 32) acc = fmaf(rp[j], row[j], acc);
#pragma unroll
    for (int o = 16; o; o >>= 1) acc += __shfl_xor_sync(0xffffffffu, acc, o);
    if (lane == 0)
        g_attn[(b * NH + warp) * SS + s] = (mask[b * SS + s] == 0) ? NEGV : acc;
}

__global__ __launch_bounds__(256) void softmax_kernel() {
    int bh = blockIdx.x, tid = threadIdx.x;
    __shared__ float red[256];
    float* p = g_attn + (size_t)bh * SS;
    float v0 = p[tid], v1 = p[tid + 256];
    red[tid] = fmaxf(v0, v1); __syncthreads();
    for (int o = 128; o; o >>= 1) { if (tid < o) red[tid] = fmaxf(red[tid], red[tid + o]); __syncthreads(); }
    float m = red[0]; __syncthreads();
    float e0 = expf(v0 - m), e1 = expf(v1 - m);
    red[tid] = e0 + e1; __syncthreads();
    for (int o = 128; o; o >>= 1) { if (tid < o) red[tid] += red[tid + o]; __syncthreads(); }
    float inv = 1.f / red[0];
    p[tid] = e0 * inv; p[tid + 256] = e1 * inv;
}

// ------------- u[b,h,:] = sum_s attn * msg_g --------------------------------
__global__ __launch_bounds__(256) void u_kernel() {
    int b = blockIdx.x, ch = blockIdx.y, tid = threadIdx.x;
    __shared__ float aw[NH][64];
    for (int t = tid; t < NH * 64; t += 256) {
        int h = t >> 6, s = t & 63;
        aw[h][s] = g_attn[(b * NH + h) * SS + ch * 64 + s];
    }
    __syncthreads();
    int j0 = tid, j1 = tid + 256, j2 = tid + 512;
    float acc[NH][3];
#pragma unroll
    for (int h = 0; h < NH; h++) { acc[h][0] = acc[h][1] = acc[h][2] = 0.f; }
    for (int s = 0; s < 64; s++) {
        const float* mr = g_msgg + (size_t)(b * SS + ch * 64 + s) * HH;
        float x0 = mr[j0], x1 = mr[j1], x2 = mr[j2];
#pragma unroll
        for (int h = 0; h < NH; h++) {
            float w = aw[h][s];
            acc[h][0] = fmaf(w, x0, acc[h][0]);
            acc[h][1] = fmaf(w, x1, acc[h][1]);
            acc[h][2] = fmaf(w, x2, acc[h][2]);
        }
    }
#pragma unroll
    for (int h = 0; h < NH; h++) {
        atomicAdd(&g_u[(b * NH + h) * HH + j0], acc[h][0]);
        atomicAdd(&g_u[(b * NH + h) * HH + j1], acc[h][1]);
        atomicAdd(&g_u[(b * NH + h) * HH + j2], acc[h][2]);
    }
}

// ------------- ctx -> wo -> LN -> MLP -> out --------------------------------
__global__ __launch_bounds__(256) void final_kernel(
    const float* __restrict__ wv, const float* __restrict__ bv,
    const float* __restrict__ wo, const float* __restrict__ bo,
    const float* __restrict__ lng, const float* __restrict__ lnb,
    const float* __restrict__ f0w, const float* __restrict__ f0b,
    const float* __restrict__ f1w, const float* __restrict__ f1b,
    const float* __restrict__ f2w, const float* __restrict__ f2b,
    float* __restrict__ out)
{
    int b = blockIdx.x, tid = threadIdx.x;
    __shared__ float u_s[NH * HH];
    __shared__ float ctx[HH], f[HH];
    __shared__ float hb1[512], hb2[128];
    __shared__ float red[256];
    for (int t = tid; t < NH * HH; t += 256) u_s[t] = g_u[(size_t)b * NH * HH + t];
    __syncthreads();
    int j0 = tid, j1 = tid + 256, j2 = tid + 512;
    {   // ctx[o] = u[h(o),:] . wv[:,o] + bv[o]
        const float* u0 = u_s + (j0 / DHD) * HH;
        const float* u1 = u_s + (j1 / DHD) * HH;
        const float* u2 = u_s + (j2 / DHD) * HH;
        float a0 = bv[j0], a1 = bv[j1], a2 = bv[j2];
        for (int i = 0; i < HH; i++) {
            const float* w = wv + (size_t)i * HH;
            a0 = fmaf(u0[i], w[j0], a0);
            a1 = fmaf(u1[i], w[j1], a1);
            a2 = fmaf(u2[i], w[j2], a2);
        }
        ctx[j0] = a0; ctx[j1] = a1; ctx[j2] = a2;
    }
    __syncthreads();
    {   // y = ctx @ wo + bo + diff_g0
        float a0 = bo[j0], a1 = bo[j1], a2 = bo[j2];
        for (int i = 0; i < HH; i++) {
            float c = ctx[i]; const float* w = wo + (size_t)i * HH;
            a0 = fmaf(c, w[j0], a0); a1 = fmaf(c, w[j1], a1); a2 = fmaf(c, w[j2], a2);
        }
        f[j0] = a0 + g_diffg0[b * HH + j0];
        f[j1] = a1 + g_diffg0[b * HH + j1];
        f[j2] = a2 + g_diffg0[b * HH + j2];
    }
    __syncthreads();
    // LayerNorm
    red[tid] = f[j0] + f[j1] + f[j2]; __syncthreads();
    for (int o = 128; o; o >>= 1) { if (tid < o) red[tid] += red[tid + o]; __syncthreads(); }
    float mu = red[0] * (1.f / HH); __syncthreads();
    float d0 = f[j0] - mu, d1 = f[j1] - mu, d2 = f[j2] - mu;
    red[tid] = d0 * d0 + d1 * d1 + d2 * d2; __syncthreads();
    for (int o = 128; o; o >>= 1) { if (tid < o) red[tid] += red[tid + o]; __syncthreads(); }
    float rs = rsqrtf(red[0] * (1.f / HH) + 1e-5f); __syncthreads();
    f[j0] = d0 * rs * lng[j0] + lnb[j0];
    f[j1] = d1 * rs * lng[j1] + lnb[j1];
    f[j2] = d2 * rs * lng[j2] + lnb[j2];
    __syncthreads();
    // fc0: 768 -> 512, relu
    {
        int o0 = tid, o1 = tid + 256;
        float a0 = f0b[o0], a1 = f0b[o1];
        for (int i = 0; i < HH; i++) {
            float x = f[i]; const float* w = f0w + (size_t)i * 512;
            a0 = fmaf(x, w[o0], a0); a1 = fmaf(x, w[o1], a1);
        }
        hb1[o0] = a0 > 0.f ? a0 : 0.f;
        hb1[o1] = a1 > 0.f ? a1 : 0.f;
    }
    __syncthreads();
    // fc1: 512 -> 128, relu
    if (tid < 128) {
        float a = f1b[tid];
        for (int i = 0; i < 512; i++) a = fmaf(hb1[i], f1w[i * 128 + tid], a);
        hb2[tid] = a > 0.f ? a : 0.f;
    }
    __syncthreads();
    // fc2: 128 -> 2
    if (tid < 2) {
        float a = f2b[tid];
        for (int i = 0; i < 128; i++) a = fmaf(hb2[i], f2w[i * 2 + tid], a);
        out[b * 2 + tid] = a;
    }
}

extern "C" void kernel_launch(void* const* d_in, const int* in_sizes, int n_in,
                              void* d_out, int out_size) {
    const float* diff  = (const float*)d_in[0];
    const float* msg   = (const float*)d_in[1];
    const int*   mask  = (const int*)d_in[2];
    const int*   ei_d  = (const int*)d_in[3];
    const int*   ei_m  = (const int*)d_in[4];
    const float* wl    = (const float*)d_in[5];
    const float* bl    = (const float*)d_in[6];
    const float* wr    = (const float*)d_in[7];
    const float* br    = (const float*)d_in[8];
    const float* att   = (const float*)d_in[9];
    const float* gbias = (const float*)d_in[10];
    const float* wq    = (const float*)d_in[11];
    const float* bq    = (const float*)d_in[12];
    const float* wk    = (const float*)d_in[13];
    const float* wv    = (const float*)d_in[15];
    const float* bv    = (const float*)d_in[16];
    const float* wo    = (const float*)d_in[17];
    const float* bo    = (const float*)d_in[18];
    const float* lng   = (const float*)d_in[19];
    const float* lnb   = (const float*)d_in[20];
    const float* f0w   = (const float*)d_in[21];
    const float* f0b   = (const float*)d_in[22];
    const float* f1w   = (const float*)d_in[23];
    const float* f1b   = (const float*)d_in[24];
    const float* f2w   = (const float*)d_in[25];
    const float* f2b   = (const float*)d_in[26];
    float* out = (float*)d_out;

    zero_kernel<<<768, 256>>>();
    dim3 gg(HH / 64, (BB * SS) / 128);
    gemm_bias_kernel<<<gg, 256>>>(msg, wl, bl, 0, BB * SS, HH, HH);
    gemm_bias_kernel<<<gg, 256>>>(msg, wr, br, 1, BB * SS, HH, HH);
    count_kernel<<<512, 256>>>(ei_m);
    scan_kernel<<<BB, 512>>>();
    scatter_kernel<<<512, 256>>>(ei_m);
    gat_node_kernel<<<dim3(SS, BB), 128>>>(att, gbias, msg);
    diff0_kernel<<<BB, 256>>>(diff, ei_d, wl, bl, wr, br, att, gbias);
    qr_kernel<<<BB, 256>>>(wq, bq, wk);
    scores_kernel<<<dim3(SS, BB), 256>>>(mask);
    softmax_kernel<<<BB * NH, 256>>>();
    u_kernel<<<dim3(BB, 8), 256>>>();
    final_kernel<<<BB, 256>>>(wv, bv, wo, bo, lng, lnb,
                              f0w, f0b, f1w, f1b, f2w, f2b, out);
}

// round 3
// speedup vs baseline: 1.3892x; 1.3892x over previous
#include <cuda_runtime.h>
#include <cuda_bf16.h>
#include <math.h>

#define BB 32
#define SS 512
#define HH 768
#define EE 4096
#define NH 8
#define DHD 96
#define NEGV -1000000000.0f
#define CAPN 256
#define CAPD 64

#define BM 128
#define BN 128
#define BKK 32

// ------------- scratch ------------------------------------------------------
__device__ float g_xl[BB * SS * HH];
__device__ float g_xr[BB * SS * HH];
__device__ float g_msgg[BB * SS * HH];
__device__ int   g_cnt[BB * SS];
__device__ int   g_off[BB * SS];
__device__ int   g_cur[BB * SS];
__device__ int   g_esrc[BB * EE];
__device__ float g_dxl[BB * CAPD * HH];
__device__ float g_diffg0[BB * HH];
__device__ float g_r[BB * NH * HH];
__device__ float g_attn[BB * NH * SS];
__device__ float g_u[BB * NH * HH];

__global__ void zero_kernel() {
    int i = blockIdx.x * 256 + threadIdx.x;
    if (i < BB * SS) g_cnt[i] = 0;
    if (i < BB * NH * HH) g_u[i] = 0.f;
}

// ------------- helpers ------------------------------------------------------
__device__ __forceinline__ unsigned f2tf32(float x) {
    unsigned r;
    asm("cvt.rna.tf32.f32 %0, %1;" : "=r"(r) : "f"(x));
    return r;
}

__device__ __forceinline__ void mma_tf32(float c[4], const unsigned a[4], const unsigned b[2]) {
    asm volatile(
        "mma.sync.aligned.m16n8k8.row.col.f32.tf32.tf32.f32 "
        "{%0,%1,%2,%3}, {%4,%5,%6,%7}, {%8,%9}, {%0,%1,%2,%3};"
        : "+f"(c[0]), "+f"(c[1]), "+f"(c[2]), "+f"(c[3])
        : "r"(a[0]), "r"(a[1]), "r"(a[2]), "r"(a[3]), "r"(b[0]), "r"(b[1]));
}

// ------------- TF32 tensor-core GEMM: C = A[M,K] @ W[K,N] + bias ------------
// M = BB*SS, N = K = HH. CTA tile 128x128, BK=32, 8 warps of 64x32.
__global__ __launch_bounds__(256) void gemm_tf32_kernel(
    const float* __restrict__ A, const float* __restrict__ W,
    const float* __restrict__ bias, int which)
{
    float* C = which ? g_xr : g_xl;
    const int N = HH, K = HH;
    __shared__ unsigned As[BM][BKK + 4];   // A[m][k], stride 36 -> frag loads conflict-free
    __shared__ unsigned Bs[BKK][BN + 4];   // B[k][n], stride 132 -> frag loads conflict-free
    int tid = threadIdx.x;
    int bm = blockIdx.y * BM, bn = blockIdx.x * BN;
    int wid = tid >> 5, lane = tid & 31;
    int wm = wid >> 2, wn = wid & 3;       // warp tile: rows wm*64, cols wn*32
    int g = lane >> 2, c = lane & 3;

    float acc[4][4][4];
#pragma unroll
    for (int i = 0; i < 4; i++)
#pragma unroll
        for (int j = 0; j < 4; j++)
#pragma unroll
            for (int t = 0; t < 4; t++) acc[i][j][t] = 0.f;

    for (int kt = 0; kt < K; kt += BKK) {
        float4 av[4], bv[4];
#pragma unroll
        for (int i = 0; i < 4; i++) {
            int lin = tid + 256 * i;           // 0..1023
            int row = lin >> 3, kq = lin & 7;  // A: 128 rows x 8 float4
            av[i] = *(const float4*)(A + (size_t)(bm + row) * K + kt + 4 * kq);
            int krow = lin >> 5, nq = lin & 31; // B: 32 rows x 32 float4
            bv[i] = *(const float4*)(W + (size_t)(kt + krow) * N + bn + 4 * nq);
        }
        __syncthreads();
#pragma unroll
        for (int i = 0; i < 4; i++) {
            int lin = tid + 256 * i;
            int row = lin >> 3, kq = (lin & 7) << 2;
            As[row][kq + 0] = f2tf32(av[i].x);
            As[row][kq + 1] = f2tf32(av[i].y);
            As[row][kq + 2] = f2tf32(av[i].z);
            As[row][kq + 3] = f2tf32(av[i].w);
            int krow = lin >> 5, nq = (lin & 31) << 2;
            Bs[krow][nq + 0] = f2tf32(bv[i].x);
            Bs[krow][nq + 1] = f2tf32(bv[i].y);
            Bs[krow][nq + 2] = f2tf32(bv[i].z);
            Bs[krow][nq + 3] = f2tf32(bv[i].w);
        }
        __syncthreads();
#pragma unroll
        for (int ks = 0; ks < 4; ks++) {
            int k0 = ks * 8;
            unsigned af[4][4], bf[4][2];
#pragma unroll
            for (int i = 0; i < 4; i++) {
                int r = wm * 64 + i * 16;
                af[i][0] = As[r + g][k0 + c];
                af[i][1] = As[r + 8 + g][k0 + c];
                af[i][2] = As[r + g][k0 + c + 4];
                af[i][3] = As[r + 8 + g][k0 + c + 4];
            }
#pragma unroll
            for (int j = 0; j < 4; j++) {
                int ncol = wn * 32 + j * 8;
                bf[j][0] = Bs[k0 + c][ncol + g];
                bf[j][1] = Bs[k0 + c + 4][ncol + g];
            }
#pragma unroll
            for (int i = 0; i < 4; i++)
#pragma unroll
                for (int j = 0; j < 4; j++)
                    mma_tf32(acc[i][j], af[i], bf[j]);
        }
        __syncthreads();
    }

#pragma unroll
    for (int i = 0; i < 4; i++) {
#pragma unroll
        for (int j = 0; j < 4; j++) {
            int row = bm + wm * 64 + i * 16 + g;
            int col = bn + wn * 32 + j * 8 + 2 * c;
            float b0 = bias[col], b1 = bias[col + 1];
            float2 o0 = make_float2(acc[i][j][0] + b0, acc[i][j][1] + b1);
            float2 o1 = make_float2(acc[i][j][2] + b0, acc[i][j][3] + b1);
            *(float2*)(C + (size_t)row * N + col) = o0;
            *(float2*)(C + (size_t)(row + 8) * N + col) = o1;
        }
    }
}

// ------------- CSR build ----------------------------------------------------
__global__ void count_kernel(const int* __restrict__ ei) {
    int idx = blockIdx.x * 256 + threadIdx.x;
    if (idx >= BB * EE) return;
    int b = idx >> 12, e = idx & 4095;
    int s = ei[b * 2 * EE + e], d = ei[b * 2 * EE + EE + e];
    if ((unsigned)s < SS && (unsigned)d < SS) atomicAdd(&g_cnt[b * SS + d], 1);
}

__global__ void scan_kernel() {
    int b = blockIdx.x, tid = threadIdx.x;
    __shared__ int sc[SS];
    int c = g_cnt[b * SS + tid];
    sc[tid] = c;
    __syncthreads();
    for (int off = 1; off < SS; off <<= 1) {
        int t = (tid >= off) ? sc[tid - off] : 0;
        __syncthreads();
        sc[tid] += t;
        __syncthreads();
    }
    int ex = sc[tid] - c;
    g_off[b * SS + tid] = ex;
    g_cur[b * SS + tid] = ex;
}

__global__ void scatter_kernel(const int* __restrict__ ei) {
    int idx = blockIdx.x * 256 + threadIdx.x;
    if (idx >= BB * EE) return;
    int b = idx >> 12, e = idx & 4095;
    int s = ei[b * 2 * EE + e], d = ei[b * 2 * EE + EE + e];
    if ((unsigned)s < SS && (unsigned)d < SS) {
        int p = atomicAdd(&g_cur[b * SS + d], 1);
        g_esrc[b * EE + p] = s;
    }
}

// ------------- msg GAT per destination node ---------------------------------
__global__ __launch_bounds__(128) void gat_node_kernel(
    const float* __restrict__ att, const float* __restrict__ gbias,
    const float* __restrict__ msg)
{
    int n = blockIdx.x, b = blockIdx.y;
    int tid = threadIdx.x;
    int node = b * SS + n;
    __shared__ float xr_s[HH], att_s[HH];
    __shared__ float ev[CAPN];
    __shared__ int srcs[CAPN];
    __shared__ float red[128];
    for (int h = tid; h < HH; h += 128) {
        xr_s[h]  = g_xr[(size_t)node * HH + h];
        att_s[h] = att[h];
    }
    int deg = g_cnt[node]; if (deg > CAPN - 1) deg = CAPN - 1;
    int base = g_off[node];
    for (int i = tid; i < deg; i += 128) srcs[i] = g_esrc[b * EE + base + i];
    if (tid == 0) srcs[deg] = n;
    __syncthreads();
    int d = deg + 1;

    int warp = tid >> 5, lane = tid & 31;
    for (int i = warp; i < d; i += 4) {
        const float* xlr = g_xl + (size_t)(b * SS + srcs[i]) * HH;
        float s = 0.f;
        for (int h = lane; h < HH; h += 32) {
            float z = xlr[h] + xr_s[h];
            z = z > 0.f ? z : 0.2f * z;
            s = fmaf(z, att_s[h], s);
        }
#pragma unroll
        for (int o = 16; o; o >>= 1) s += __shfl_xor_sync(0xffffffffu, s, o);
        if (lane == 0) ev[i] = s;
    }
    __syncthreads();

    float m = -3.4e38f;
    for (int i = tid; i < d; i += 128) m = fmaxf(m, ev[i]);
    red[tid] = m; __syncthreads();
    for (int o = 64; o; o >>= 1) { if (tid < o) red[tid] = fmaxf(red[tid], red[tid + o]); __syncthreads(); }
    float emax = red[0]; __syncthreads();
    float ssum = 0.f;
    for (int i = tid; i < d; i += 128) { float p = expf(ev[i] - emax); ev[i] = p; ssum += p; }
    red[tid] = ssum; __syncthreads();
    for (int o = 64; o; o >>= 1) { if (tid < o) red[tid] += red[tid + o]; __syncthreads(); }
    float inv = 1.f / red[0];
    __syncthreads();

    for (int h = tid; h < HH; h += 128) {
        float a = 0.f;
        for (int i = 0; i < d; i++)
            a = fmaf(ev[i], g_xl[(size_t)(b * SS + srcs[i]) * HH + h], a);
        g_msgg[(size_t)node * HH + h] = a * inv + gbias[h] + msg[(size_t)node * HH + h];
    }
}

// ------------- diff GAT at node 0 only (per batch) --------------------------
__global__ __launch_bounds__(256) void diff0_kernel(
    const float* __restrict__ diff, const int* __restrict__ ei,
    const float* __restrict__ wl, const float* __restrict__ bl,
    const float* __restrict__ wr, const float* __restrict__ br,
    const float* __restrict__ att, const float* __restrict__ gbias)
{
    int b = blockIdx.x, tid = threadIdx.x;
    __shared__ float xrows[8][HH];
    __shared__ float xr0[HH], x0s[HH];
    __shared__ float evals[CAPD];
    __shared__ int srcs[CAPD];
    __shared__ float red[256];
    __shared__ int scnt;
    if (tid == 0) scnt = 0;
    const float* x0 = diff + (size_t)b * SS * HH;
    for (int j = tid; j < HH; j += 256) x0s[j] = x0[j];
    __syncthreads();
    int j0 = tid, j1 = tid + 256, j2 = tid + 512;
    {   // xr0 = x0 @ wr + br
        float a0 = br[j0], a1 = br[j1], a2 = br[j2];
        for (int i = 0; i < HH; i++) {
            float x = x0s[i]; const float* w = wr + (size_t)i * HH;
            a0 = fmaf(x, w[j0], a0); a1 = fmaf(x, w[j1], a1); a2 = fmaf(x, w[j2], a2);
        }
        xr0[j0] = a0; xr0[j1] = a1; xr0[j2] = a2;
    }
    for (int e = tid; e < EE; e += 256) {
        int s = ei[b * 2 * EE + e], dd = ei[b * 2 * EE + EE + e];
        if ((unsigned)s < SS && dd == 0) {
            int p = atomicAdd(&scnt, 1);
            if (p < CAPD - 1) srcs[p] = s;
        }
    }
    __syncthreads();
    int nd = min(scnt, CAPD - 1);
    if (tid == 0) srcs[nd] = 0;
    __syncthreads();
    int d = nd + 1;

    for (int c0 = 0; c0 < d; c0 += 8) {
        int nc = min(8, d - c0);
        for (int t = tid; t < nc * HH; t += 256) {
            int s = t / HH, j = t - s * HH;
            xrows[s][j] = diff[((size_t)b * SS + srcs[c0 + s]) * HH + j];
        }
        __syncthreads();
        float acc[8][3];
#pragma unroll
        for (int s = 0; s < 8; s++) { acc[s][0] = bl[j0]; acc[s][1] = bl[j1]; acc[s][2] = bl[j2]; }
        for (int i = 0; i < HH; i++) {
            const float* w = wl + (size_t)i * HH;
            float w0 = w[j0], w1 = w[j1], w2 = w[j2];
#pragma unroll
            for (int s = 0; s < 8; s++) {
                float x = xrows[s][i];
                acc[s][0] = fmaf(x, w0, acc[s][0]);
                acc[s][1] = fmaf(x, w1, acc[s][1]);
                acc[s][2] = fmaf(x, w2, acc[s][2]);
            }
        }
        for (int s = 0; s < nc; s++) {
            float* xp = g_dxl + ((size_t)b * CAPD + c0 + s) * HH;
            xp[j0] = acc[s][0]; xp[j1] = acc[s][1]; xp[j2] = acc[s][2];
            float z0 = acc[s][0] + xr0[j0]; z0 = z0 > 0.f ? z0 : 0.2f * z0;
            float z1 = acc[s][1] + xr0[j1]; z1 = z1 > 0.f ? z1 : 0.2f * z1;
            float z2 = acc[s][2] + xr0[j2]; z2 = z2 > 0.f ? z2 : 0.2f * z2;
            red[tid] = z0 * att[j0] + z1 * att[j1] + z2 * att[j2];
            __syncthreads();
            for (int o = 128; o; o >>= 1) { if (tid < o) red[tid] += red[tid + o]; __syncthreads(); }
            if (tid == 0) evals[c0 + s] = red[0];
            __syncthreads();
        }
    }
    float m = -3.4e38f;
    for (int i = tid; i < d; i += 256) m = fmaxf(m, evals[i]);
    red[tid] = m; __syncthreads();
    for (int o = 128; o; o >>= 1) { if (tid < o) red[tid] = fmaxf(red[tid], red[tid + o]); __syncthreads(); }
    float emax = red[0]; __syncthreads();
    float ssum = 0.f;
    for (int i = tid; i < d; i += 256) { float p = expf(evals[i] - emax); evals[i] = p; ssum += p; }
    red[tid] = ssum; __syncthreads();
    for (int o = 128; o; o >>= 1) { if (tid < o) red[tid] += red[tid + o]; __syncthreads(); }
    float inv = 1.f / red[0];
    __syncthreads();
    float o0 = 0.f, o1 = 0.f, o2 = 0.f;
    for (int s = 0; s < d; s++) {
        const float* xp = g_dxl + ((size_t)b * CAPD + s) * HH;
        float al = evals[s] * inv;
        o0 = fmaf(al, xp[j0], o0);
        o1 = fmaf(al, xp[j1], o1);
        o2 = fmaf(al, xp[j2], o2);
    }
    g_diffg0[b * HH + j0] = o0 + gbias[j0] + x0s[j0];
    g_diffg0[b * HH + j1] = o1 + gbias[j1] + x0s[j1];
    g_diffg0[b * HH + j2] = o2 + gbias[j2] + x0s[j2];
}

// ------------- q0 and folded r ----------------------------------------------
__global__ __launch_bounds__(256) void qr_kernel(
    const float* __restrict__ wq, const float* __restrict__ bq,
    const float* __restrict__ wk)
{
    int b = blockIdx.x, tid = threadIdx.x;
    __shared__ float x[HH], q0[HH];
    for (int j = tid; j < HH; j += 256) x[j] = g_diffg0[b * HH + j];
    __syncthreads();
    int j0 = tid, j1 = tid + 256, j2 = tid + 512;
    {
        float a0 = bq[j0], a1 = bq[j1], a2 = bq[j2];
        for (int i = 0; i < HH; i++) {
            float xv = x[i]; const float* w = wq + (size_t)i * HH;
            a0 = fmaf(xv, w[j0], a0); a1 = fmaf(xv, w[j1], a1); a2 = fmaf(xv, w[j2], a2);
        }
        q0[j0] = a0; q0[j1] = a1; q0[j2] = a2;
    }
    __syncthreads();
    const float RS = 0.10206207261596577f;  // 1/sqrt(96)
    for (int t = tid; t < NH * HH; t += 256) {
        int h = t / HH, i = t - h * HH;
        const float4* wp = (const float4*)(wk + (size_t)i * HH + h * DHD);
        const float4* qp = (const float4*)(q0 + h * DHD);
        float s = 0.f;
#pragma unroll
        for (int d4 = 0; d4 < DHD / 4; d4++) {
            float4 w4 = wp[d4]; float4 q4 = qp[d4];
            s = fmaf(w4.x, q4.x, s); s = fmaf(w4.y, q4.y, s);
            s = fmaf(w4.z, q4.z, s); s = fmaf(w4.w, q4.w, s);
        }
        g_r[(b * NH + h) * HH + i] = s * RS;
    }
}

// ------------- scores -------------------------------------------------------
__global__ __launch_bounds__(256) void scores_kernel(const int* __restrict__ mask) {
    int s = blockIdx.x, b = blockIdx.y, tid = threadIdx.x;
    __shared__ float row[HH];
    for (int j = tid; j < HH; j += 256) row[j] = g_msgg[(size_t)(b * SS + s) * HH + j];
    __syncthreads();
    int warp = tid >> 5, lane = tid & 31;   // warp == head
    const float* rp = g_r + (size_t)(b * NH + warp) * HH;
    float acc = 0.f;
    for (int j = lane; j < HH; j += 32) acc = fmaf(rp[j], row[j], acc);
#pragma unroll
    for (int o = 16; o; o >>= 1) acc += __shfl_xor_sync(0xffffffffu, acc, o);
    if (lane == 0)
        g_attn[(b * NH + warp) * SS + s] = (mask[b * SS + s] == 0) ? NEGV : acc;
}

__global__ __launch_bounds__(256) void softmax_kernel() {
    int bh = blockIdx.x, tid = threadIdx.x;
    __shared__ float red[256];
    float* p = g_attn + (size_t)bh * SS;
    float v0 = p[tid], v1 = p[tid + 256];
    red[tid] = fmaxf(v0, v1); __syncthreads();
    for (int o = 128; o; o >>= 1) { if (tid < o) red[tid] = fmaxf(red[tid], red[tid + o]); __syncthreads(); }
    float m = red[0]; __syncthreads();
    float e0 = expf(v0 - m), e1 = expf(v1 - m);
    red[tid] = e0 + e1; __syncthreads();
    for (int o = 128; o; o >>= 1) { if (tid < o) red[tid] += red[tid + o]; __syncthreads(); }
    float inv = 1.f / red[0];
    p[tid] = e0 * inv; p[tid + 256] = e1 * inv;
}

// ------------- u[b,h,:] = sum_s attn * msg_g --------------------------------
__global__ __launch_bounds__(256) void u_kernel() {
    int b = blockIdx.x, ch = blockIdx.y, tid = threadIdx.x;
    __shared__ float aw[NH][64];
    for (int t = tid; t < NH * 64; t += 256) {
        int h = t >> 6, s = t & 63;
        aw[h][s] = g_attn[(b * NH + h) * SS + ch * 64 + s];
    }
    __syncthreads();
    int j0 = tid, j1 = tid + 256, j2 = tid + 512;
    float acc[NH][3];
#pragma unroll
    for (int h = 0; h < NH; h++) { acc[h][0] = acc[h][1] = acc[h][2] = 0.f; }
    for (int s = 0; s < 64; s++) {
        const float* mr = g_msgg + (size_t)(b * SS + ch * 64 + s) * HH;
        float x0 = mr[j0], x1 = mr[j1], x2 = mr[j2];
#pragma unroll
        for (int h = 0; h < NH; h++) {
            float w = aw[h][s];
            acc[h][0] = fmaf(w, x0, acc[h][0]);
            acc[h][1] = fmaf(w, x1, acc[h][1]);
            acc[h][2] = fmaf(w, x2, acc[h][2]);
        }
    }
#pragma unroll
    for (int h = 0; h < NH; h++) {
        atomicAdd(&g_u[(b * NH + h) * HH + j0], acc[h][0]);
        atomicAdd(&g_u[(b * NH + h) * HH + j1], acc[h][1]);
        atomicAdd(&g_u[(b * NH + h) * HH + j2], acc[h][2]);
    }
}

// ------------- ctx -> wo -> LN -> MLP -> out --------------------------------
__global__ __launch_bounds__(256) void final_kernel(
    const float* __restrict__ wv, const float* __restrict__ bv,
    const float* __restrict__ wo, const float* __restrict__ bo,
    const float* __restrict__ lng, const float* __restrict__ lnb,
    const float* __restrict__ f0w, const float* __restrict__ f0b,
    const float* __restrict__ f1w, const float* __restrict__ f1b,
    const float* __restrict__ f2w, const float* __restrict__ f2b,
    float* __restrict__ out)
{
    int b = blockIdx.x, tid = threadIdx.x;
    __shared__ float u_s[NH * HH];
    __shared__ float ctx[HH], f[HH];
    __shared__ float hb1[512], hb2[128];
    __shared__ float red[256];
    for (int t = tid; t < NH * HH; t += 256) u_s[t] = g_u[(size_t)b * NH * HH + t];
    __syncthreads();
    int j0 = tid, j1 = tid + 256, j2 = tid + 512;
    {   // ctx[o] = u[h(o),:] . wv[:,o] + bv[o]
        const float* u0 = u_s + (j0 / DHD) * HH;
        const float* u1 = u_s + (j1 / DHD) * HH;
        const float* u2 = u_s + (j2 / DHD) * HH;
        float a0 = bv[j0], a1 = bv[j1], a2 = bv[j2];
        for (int i = 0; i < HH; i++) {
            const float* w = wv + (size_t)i * HH;
            a0 = fmaf(u0[i], w[j0], a0);
            a1 = fmaf(u1[i], w[j1], a1);
            a2 = fmaf(u2[i], w[j2], a2);
        }
        ctx[j0] = a0; ctx[j1] = a1; ctx[j2] = a2;
    }
    __syncthreads();
    {   // y = ctx @ wo + bo + diff_g0
        float a0 = bo[j0], a1 = bo[j1], a2 = bo[j2];
        for (int i = 0; i < HH; i++) {
            float c = ctx[i]; const float* w = wo + (size_t)i * HH;
            a0 = fmaf(c, w[j0], a0); a1 = fmaf(c, w[j1], a1); a2 = fmaf(c, w[j2], a2);
        }
        f[j0] = a0 + g_diffg0[b * HH + j0];
        f[j1] = a1 + g_diffg0[b * HH + j1];
        f[j2] = a2 + g_diffg0[b * HH + j2];
    }
    __syncthreads();
    // LayerNorm
    red[tid] = f[j0] + f[j1] + f[j2]; __syncthreads();
    for (int o = 128; o; o >>= 1) { if (tid < o) red[tid] += red[tid + o]; __syncthreads(); }
    float mu = red[0] * (1.f / HH); __syncthreads();
    float d0 = f[j0] - mu, d1 = f[j1] - mu, d2 = f[j2] - mu;
    red[tid] = d0 * d0 + d1 * d1 + d2 * d2; __syncthreads();
    for (int o = 128; o; o >>= 1) { if (tid < o) red[tid] += red[tid + o]; __syncthreads(); }
    float rs = rsqrtf(red[0] * (1.f / HH) + 1e-5f); __syncthreads();
    f[j0] = d0 * rs * lng[j0] + lnb[j0];
    f[j1] = d1 * rs * lng[j1] + lnb[j1];
    f[j2] = d2 * rs * lng[j2] + lnb[j2];
    __syncthreads();
    // fc0: 768 -> 512, relu
    {
        int o0 = tid, o1 = tid + 256;
        float a0 = f0b[o0], a1 = f0b[o1];
        for (int i = 0; i < HH; i++) {
            float x = f[i]; const float* w = f0w + (size_t)i * 512;
            a0 = fmaf(x, w[o0], a0); a1 = fmaf(x, w[o1], a1);
        }
        hb1[o0] = a0 > 0.f ? a0 : 0.f;
        hb1[o1] = a1 > 0.f ? a1 : 0.f;
    }
    __syncthreads();
    // fc1: 512 -> 128, relu
    if (tid < 128) {
        float a = f1b[tid];
        for (int i = 0; i < 512; i++) a = fmaf(hb1[i], f1w[i * 128 + tid], a);
        hb2[tid] = a > 0.f ? a : 0.f;
    }
    __syncthreads();
    // fc2: 128 -> 2
    if (tid < 2) {
        float a = f2b[tid];
        for (int i = 0; i < 128; i++) a = fmaf(hb2[i], f2w[i * 2 + tid], a);
        out[b * 2 + tid] = a;
    }
}

extern "C" void kernel_launch(void* const* d_in, const int* in_sizes, int n_in,
                              void* d_out, int out_size) {
    const float* diff  = (const float*)d_in[0];
    const float* msg   = (const float*)d_in[1];
    const int*   mask  = (const int*)d_in[2];
    const int*   ei_d  = (const int*)d_in[3];
    const int*   ei_m  = (const int*)d_in[4];
    const float* wl    = (const float*)d_in[5];
    const float* bl    = (const float*)d_in[6];
    const float* wr    = (const float*)d_in[7];
    const float* br    = (const float*)d_in[8];
    const float* att   = (const float*)d_in[9];
    const float* gbias = (const float*)d_in[10];
    const float* wq    = (const float*)d_in[11];
    const float* bq    = (const float*)d_in[12];
    const float* wk    = (const float*)d_in[13];
    const float* wv    = (const float*)d_in[15];
    const float* bv    = (const float*)d_in[16];
    const float* wo    = (const float*)d_in[17];
    const float* bo    = (const float*)d_in[18];
    const float* lng   = (const float*)d_in[19];
    const float* lnb   = (const float*)d_in[20];
    const float* f0w   = (const float*)d_in[21];
    const float* f0b   = (const float*)d_in[22];
    const float* f1w   = (const float*)d_in[23];
    const float* f1b   = (const float*)d_in[24];
    const float* f2w   = (const float*)d_in[25];
    const float* f2b   = (const float*)d_in[26];
    float* out = (float*)d_out;

    zero_kernel<<<768, 256>>>();
    dim3 gg(HH / BN, (BB * SS) / BM);
    gemm_tf32_kernel<<<gg, 256>>>(msg, wl, bl, 0);
    gemm_tf32_kernel<<<gg, 256>>>(msg, wr, br, 1);
    count_kernel<<<512, 256>>>(ei_m);
    scan_kernel<<<BB, 512>>>();
    scatter_kernel<<<512, 256>>>(ei_m);
    gat_node_kernel<<<dim3(SS, BB), 128>>>(att, gbias, msg);
    diff0_kernel<<<BB, 256>>>(diff, ei_d, wl, bl, wr, br, att, gbias);
    qr_kernel<<<BB, 256>>>(wq, bq, wk);
    scores_kernel<<<dim3(SS, BB), 256>>>(mask);
    softmax_kernel<<<BB * NH, 256>>>();
    u_kernel<<<dim3(BB, 8), 256>>>();
    final_kernel<<<BB, 256>>>(wv, bv, wo, bo, lng, lnb,
                              f0w, f0b, f1w, f1b, f2w, f2b, out);
}

// round 4
// speedup vs baseline: 1.4769x; 1.0631x over previous
#include <cuda_runtime.h>
#include <cuda_bf16.h>
#include <math.h>

#define BB 32
#define SS 512
#define HH 768
#define EE 4096
#define NH 8
#define DHD 96
#define NEGV -1000000000.0f
#define CAPD 64

#define BM 128
#define BN 128
#define BKK 32

// ------------- scratch ------------------------------------------------------
__device__ float g_xl[BB * SS * HH];
__device__ float g_xr[BB * SS * HH];
__device__ float g_msgg[BB * SS * HH];
__device__ int   g_cnt[BB * SS];
__device__ int   g_off[BB * SS];
__device__ int   g_cur[BB * SS];
__device__ int   g_esrc[BB * EE];
__device__ float g_dxl[BB * CAPD * HH];
__device__ float g_diffg0[BB * HH];
__device__ float g_r[BB * NH * HH];
__device__ float g_attn[BB * NH * SS];
__device__ float g_u[BB * NH * HH];

__global__ void zero_kernel() {
    int i = blockIdx.x * 256 + threadIdx.x;
    if (i < BB * SS) g_cnt[i] = 0;
    if (i < BB * NH * HH) g_u[i] = 0.f;
}

// ------------- helpers ------------------------------------------------------
__device__ __forceinline__ void mma_tf32(float c[4], const unsigned a[4], const unsigned b[2]) {
    asm volatile(
        "mma.sync.aligned.m16n8k8.row.col.f32.tf32.tf32.f32 "
        "{%0,%1,%2,%3}, {%4,%5,%6,%7}, {%8,%9}, {%0,%1,%2,%3};"
        : "+f"(c[0]), "+f"(c[1]), "+f"(c[2]), "+f"(c[3])
        : "r"(a[0]), "r"(a[1]), "r"(a[2]), "r"(a[3]), "r"(b[0]), "r"(b[1]));
}

// ------------- fused TF32 GEMM: {g_xl,g_xr} = A @ {wl,wr} + {bl,br} ---------
// M = BB*SS = 16384, N = K = 768. CTA 128x128, BK=32, 8 warps of 64x32.
// Raw fp32 bits fed to mma.tf32 (HW truncation). Register prefetch of next tile.
__global__ __launch_bounds__(256) void gemm_fused_kernel(
    const float* __restrict__ A,
    const float* __restrict__ Wl, const float* __restrict__ Wr,
    const float* __restrict__ bl, const float* __restrict__ br)
{
    const int N = HH, K = HH;
    int bx = blockIdx.x;
    const float* W  = (bx < 6) ? Wl : Wr;
    const float* bias = (bx < 6) ? bl : br;
    float* C = (bx < 6) ? g_xl : g_xr;
    int bn = (bx < 6 ? bx : bx - 6) * BN;
    int bm = blockIdx.y * BM;

    __shared__ float As[BM][BKK + 4];   // stride 36 floats (144B, 16B-aligned)
    __shared__ float Bs[BKK][BN + 4];   // stride 132 floats (528B, 16B-aligned)
    int tid = threadIdx.x;
    int wid = tid >> 5, lane = tid & 31;
    int wm = wid >> 2, wn = wid & 3;
    int g = lane >> 2, c = lane & 3;

    float acc[4][4][4];
#pragma unroll
    for (int i = 0; i < 4; i++)
#pragma unroll
        for (int j = 0; j < 4; j++)
#pragma unroll
            for (int t = 0; t < 4; t++) acc[i][j][t] = 0.f;

    int arow = tid >> 3, akq = tid & 7;     // A: 128 rows x 8 float4 per 256-thread pass
    int brow = tid >> 5, bnq = tid & 31;    // B: 32 rows x 32 float4

    float4 av[4], bv[4];
#pragma unroll
    for (int i = 0; i < 4; i++) {
        int lin = tid + 256 * i;
        int r = lin >> 3, kq = lin & 7;
        av[i] = *(const float4*)(A + (size_t)(bm + r) * K + 4 * kq);
        int kr = lin >> 5, nq = lin & 31;
        bv[i] = *(const float4*)(W + (size_t)kr * N + bn + 4 * nq);
    }
    (void)arow; (void)akq; (void)brow; (void)bnq;

    for (int kt = 0; kt < K; kt += BKK) {
#pragma unroll
        for (int i = 0; i < 4; i++) {
            int lin = tid + 256 * i;
            int r = lin >> 3, kq = lin & 7;
            *(float4*)&As[r][kq << 2] = av[i];
            int kr = lin >> 5, nq = lin & 31;
            *(float4*)&Bs[kr][nq << 2] = bv[i];
        }
        __syncthreads();
        // prefetch next tile into registers (overlaps with MMA below)
        if (kt + BKK < K) {
#pragma unroll
            for (int i = 0; i < 4; i++) {
                int lin = tid + 256 * i;
                int r = lin >> 3, kq = lin & 7;
                av[i] = *(const float4*)(A + (size_t)(bm + r) * K + kt + BKK + 4 * kq);
                int kr = lin >> 5, nq = lin & 31;
                bv[i] = *(const float4*)(W + (size_t)(kt + BKK + kr) * N + bn + 4 * nq);
            }
        }
#pragma unroll
        for (int ks = 0; ks < 4; ks++) {
            int k0 = ks * 8;
            unsigned af[4][4], bf[4][2];
#pragma unroll
            for (int i = 0; i < 4; i++) {
                int r = wm * 64 + i * 16;
                af[i][0] = __float_as_uint(As[r + g][k0 + c]);
                af[i][1] = __float_as_uint(As[r + 8 + g][k0 + c]);
                af[i][2] = __float_as_uint(As[r + g][k0 + c + 4]);
                af[i][3] = __float_as_uint(As[r + 8 + g][k0 + c + 4]);
            }
#pragma unroll
            for (int j = 0; j < 4; j++) {
                int ncol = wn * 32 + j * 8;
                bf[j][0] = __float_as_uint(Bs[k0 + c][ncol + g]);
                bf[j][1] = __float_as_uint(Bs[k0 + c + 4][ncol + g]);
            }
#pragma unroll
            for (int i = 0; i < 4; i++)
#pragma unroll
                for (int j = 0; j < 4; j++)
                    mma_tf32(acc[i][j], af[i], bf[j]);
        }
        __syncthreads();
    }

#pragma unroll
    for (int i = 0; i < 4; i++) {
#pragma unroll
        for (int j = 0; j < 4; j++) {
            int row = bm + wm * 64 + i * 16 + g;
            int col = bn + wn * 32 + j * 8 + 2 * c;
            float b0 = bias[col], b1 = bias[col + 1];
            float2 o0 = make_float2(acc[i][j][0] + b0, acc[i][j][1] + b1);
            float2 o1 = make_float2(acc[i][j][2] + b0, acc[i][j][3] + b1);
            *(float2*)(C + (size_t)row * N + col) = o0;
            *(float2*)(C + (size_t)(row + 8) * N + col) = o1;
        }
    }
}

// ------------- CSR build ----------------------------------------------------
__global__ void count_kernel(const int* __restrict__ ei) {
    int idx = blockIdx.x * 256 + threadIdx.x;
    if (idx >= BB * EE) return;
    int b = idx >> 12, e = idx & 4095;
    int s = ei[b * 2 * EE + e], d = ei[b * 2 * EE + EE + e];
    if ((unsigned)s < SS && (unsigned)d < SS) atomicAdd(&g_cnt[b * SS + d], 1);
}

__global__ void scan_kernel() {
    int b = blockIdx.x, tid = threadIdx.x;
    __shared__ int sc[SS];
    int c = g_cnt[b * SS + tid];
    sc[tid] = c;
    __syncthreads();
    for (int off = 1; off < SS; off <<= 1) {
        int t = (tid >= off) ? sc[tid - off] : 0;
        __syncthreads();
        sc[tid] += t;
        __syncthreads();
    }
    int ex = sc[tid] - c;
    g_off[b * SS + tid] = ex;
    g_cur[b * SS + tid] = ex;
}

__global__ void scatter_kernel(const int* __restrict__ ei) {
    int idx = blockIdx.x * 256 + threadIdx.x;
    if (idx >= BB * EE) return;
    int b = idx >> 12, e = idx & 4095;
    int s = ei[b * 2 * EE + e], d = ei[b * 2 * EE + EE + e];
    if ((unsigned)s < SS && (unsigned)d < SS) {
        int p = atomicAdd(&g_cur[b * SS + d], 1);
        g_esrc[b * EE + p] = s;
    }
}

// ------------- msg GAT: one-pass online softmax per dst node -----------------
__global__ __launch_bounds__(128) void gat_node_kernel(
    const float* __restrict__ att, const float* __restrict__ gbias,
    const float* __restrict__ msg)
{
    int n = blockIdx.x, b = blockIdx.y, tid = threadIdx.x;
    int node = b * SS + n;
    __shared__ float red[4];
    int warp = tid >> 5, lane = tid & 31;

    float xr_r[6], att_r[6], acc[6];
#pragma unroll
    for (int j = 0; j < 6; j++) {
        int h = tid + 128 * j;
        xr_r[j]  = g_xr[(size_t)node * HH + h];
        att_r[j] = att[h];
        acc[j] = 0.f;
    }
    int deg = g_cnt[node];
    int base = b * EE + g_off[node];
    float m = -3.4e38f, ssum = 0.f;

    for (int i = 0; i <= deg; i++) {
        int src = (i < deg) ? g_esrc[base + i] : n;   // self-loop last
        const float* row = g_xl + (size_t)(b * SS + src) * HH;
        float vj[6], part = 0.f;
#pragma unroll
        for (int j = 0; j < 6; j++) {
            float v = row[tid + 128 * j];
            vj[j] = v;
            float z = v + xr_r[j];
            z = z > 0.f ? z : 0.2f * z;
            part = fmaf(z, att_r[j], part);
        }
#pragma unroll
        for (int o = 16; o; o >>= 1) part += __shfl_xor_sync(0xffffffffu, part, o);
        if (lane == 0) red[warp] = part;
        __syncthreads();
        float e = red[0] + red[1] + red[2] + red[3];
        __syncthreads();
        float mn = fmaxf(m, e);
        float scale = __expf(m - mn);
        float p = __expf(e - mn);
        ssum = ssum * scale + p;
#pragma unroll
        for (int j = 0; j < 6; j++) acc[j] = fmaf(acc[j], scale, p * vj[j]);
        m = mn;
    }
    float inv = 1.f / ssum;
#pragma unroll
    for (int j = 0; j < 6; j++) {
        int h = tid + 128 * j;
        g_msgg[(size_t)node * HH + h] = acc[j] * inv + gbias[h] + msg[(size_t)node * HH + h];
    }
}

// ------------- diff GAT at node 0 only (per batch) --------------------------
__global__ __launch_bounds__(256) void diff0_kernel(
    const float* __restrict__ diff, const int* __restrict__ ei,
    const float* __restrict__ wl, const float* __restrict__ bl,
    const float* __restrict__ wr, const float* __restrict__ br,
    const float* __restrict__ att, const float* __restrict__ gbias)
{
    int b = blockIdx.x, tid = threadIdx.x;
    __shared__ float xrows[8][HH];
    __shared__ float xr0[HH], x0s[HH];
    __shared__ float evals[CAPD];
    __shared__ int srcs[CAPD];
    __shared__ float red[256];
    __shared__ int scnt;
    if (tid == 0) scnt = 0;
    const float* x0 = diff + (size_t)b * SS * HH;
    for (int j = tid; j < HH; j += 256) x0s[j] = x0[j];
    __syncthreads();
    int j0 = tid, j1 = tid + 256, j2 = tid + 512;
    {   // xr0 = x0 @ wr + br
        float a0 = br[j0], a1 = br[j1], a2 = br[j2];
        for (int i = 0; i < HH; i++) {
            float x = x0s[i]; const float* w = wr + (size_t)i * HH;
            a0 = fmaf(x, w[j0], a0); a1 = fmaf(x, w[j1], a1); a2 = fmaf(x, w[j2], a2);
        }
        xr0[j0] = a0; xr0[j1] = a1; xr0[j2] = a2;
    }
    for (int e = tid; e < EE; e += 256) {
        int s = ei[b * 2 * EE + e], dd = ei[b * 2 * EE + EE + e];
        if ((unsigned)s < SS && dd == 0) {
            int p = atomicAdd(&scnt, 1);
            if (p < CAPD - 1) srcs[p] = s;
        }
    }
    __syncthreads();
    int nd = min(scnt, CAPD - 1);
    if (tid == 0) srcs[nd] = 0;
    __syncthreads();
    int d = nd + 1;

    for (int c0 = 0; c0 < d; c0 += 8) {
        int nc = min(8, d - c0);
        for (int t = tid; t < nc * HH; t += 256) {
            int s = t / HH, j = t - s * HH;
            xrows[s][j] = diff[((size_t)b * SS + srcs[c0 + s]) * HH + j];
        }
        __syncthreads();
        float acc[8][3];
#pragma unroll
        for (int s = 0; s < 8; s++) { acc[s][0] = bl[j0]; acc[s][1] = bl[j1]; acc[s][2] = bl[j2]; }
        for (int i = 0; i < HH; i++) {
            const float* w = wl + (size_t)i * HH;
            float w0 = w[j0], w1 = w[j1], w2 = w[j2];
#pragma unroll
            for (int s = 0; s < 8; s++) {
                float x = xrows[s][i];
                acc[s][0] = fmaf(x, w0, acc[s][0]);
                acc[s][1] = fmaf(x, w1, acc[s][1]);
                acc[s][2] = fmaf(x, w2, acc[s][2]);
            }
        }
        for (int s = 0; s < nc; s++) {
            float* xp = g_dxl + ((size_t)b * CAPD + c0 + s) * HH;
            xp[j0] = acc[s][0]; xp[j1] = acc[s][1]; xp[j2] = acc[s][2];
            float z0 = acc[s][0] + xr0[j0]; z0 = z0 > 0.f ? z0 : 0.2f * z0;
            float z1 = acc[s][1] + xr0[j1]; z1 = z1 > 0.f ? z1 : 0.2f * z1;
            float z2 = acc[s][2] + xr0[j2]; z2 = z2 > 0.f ? z2 : 0.2f * z2;
            red[tid] = z0 * att[j0] + z1 * att[j1] + z2 * att[j2];
            __syncthreads();
            for (int o = 128; o; o >>= 1) { if (tid < o) red[tid] += red[tid + o]; __syncthreads(); }
            if (tid == 0) evals[c0 + s] = red[0];
            __syncthreads();
        }
    }
    float m = -3.4e38f;
    for (int i = tid; i < d; i += 256) m = fmaxf(m, evals[i]);
    red[tid] = m; __syncthreads();
    for (int o = 128; o; o >>= 1) { if (tid < o) red[tid] = fmaxf(red[tid], red[tid + o]); __syncthreads(); }
    float emax = red[0]; __syncthreads();
    float ssum = 0.f;
    for (int i = tid; i < d; i += 256) { float p = expf(evals[i] - emax); evals[i] = p; ssum += p; }
    red[tid] = ssum; __syncthreads();
    for (int o = 128; o; o >>= 1) { if (tid < o) red[tid] += red[tid + o]; __syncthreads(); }
    float inv = 1.f / red[0];
    __syncthreads();
    float o0 = 0.f, o1 = 0.f, o2 = 0.f;
    for (int s = 0; s < d; s++) {
        const float* xp = g_dxl + ((size_t)b * CAPD + s) * HH;
        float al = evals[s] * inv;
        o0 = fmaf(al, xp[j0], o0);
        o1 = fmaf(al, xp[j1], o1);
        o2 = fmaf(al, xp[j2], o2);
    }
    g_diffg0[b * HH + j0] = o0 + gbias[j0] + x0s[j0];
    g_diffg0[b * HH + j1] = o1 + gbias[j1] + x0s[j1];
    g_diffg0[b * HH + j2] = o2 + gbias[j2] + x0s[j2];
}

// ------------- q0 and folded r ----------------------------------------------
__global__ __launch_bounds__(256) void qr_kernel(
    const float* __restrict__ wq, const float* __restrict__ bq,
    const float* __restrict__ wk)
{
    int b = blockIdx.x, tid = threadIdx.x;
    __shared__ float x[HH], q0[HH];
    for (int j = tid; j < HH; j += 256) x[j] = g_diffg0[b * HH + j];
    __syncthreads();
    int j0 = tid, j1 = tid + 256, j2 = tid + 512;
    {
        float a0 = bq[j0], a1 = bq[j1], a2 = bq[j2];
        for (int i = 0; i < HH; i++) {
            float xv = x[i]; const float* w = wq + (size_t)i * HH;
            a0 = fmaf(xv, w[j0], a0); a1 = fmaf(xv, w[j1], a1); a2 = fmaf(xv, w[j2], a2);
        }
        q0[j0] = a0; q0[j1] = a1; q0[j2] = a2;
    }
    __syncthreads();
    const float RS = 0.10206207261596577f;  // 1/sqrt(96)
    for (int t = tid; t < NH * HH; t += 256) {
        int h = t / HH, i = t - h * HH;
        const float4* wp = (const float4*)(wk + (size_t)i * HH + h * DHD);
        const float4* qp = (const float4*)(q0 + h * DHD);
        float s = 0.f;
#pragma unroll
        for (int d4 = 0; d4 < DHD / 4; d4++) {
            float4 w4 = wp[d4]; float4 q4 = qp[d4];
            s = fmaf(w4.x, q4.x, s); s = fmaf(w4.y, q4.y, s);
            s = fmaf(w4.z, q4.z, s); s = fmaf(w4.w, q4.w, s);
        }
        g_r[(b * NH + h) * HH + i] = s * RS;
    }
}

// ------------- scores -------------------------------------------------------
__global__ __launch_bounds__(256) void scores_kernel(const int* __restrict__ mask) {
    int s = blockIdx.x, b = blockIdx.y, tid = threadIdx.x;
    __shared__ float row[HH];
    for (int j = tid; j < HH; j += 256) row[j] = g_msgg[(size_t)(b * SS + s) * HH + j];
    __syncthreads();
    int warp = tid >> 5, lane = tid & 31;   // warp == head
    const float* rp = g_r + (size_t)(b * NH + warp) * HH;
    float acc = 0.f;
    for (int j = lane; j < HH; j += 32) acc = fmaf(rp[j], row[j], acc);
#pragma unroll
    for (int o = 16; o; o >>= 1) acc += __shfl_xor_sync(0xffffffffu, acc, o);
    if (lane == 0)
        g_attn[(b * NH + warp) * SS + s] = (mask[b * SS + s] == 0) ? NEGV : acc;
}

__global__ __launch_bounds__(256) void softmax_kernel() {
    int bh = blockIdx.x, tid = threadIdx.x;
    __shared__ float red[256];
    float* p = g_attn + (size_t)bh * SS;
    float v0 = p[tid], v1 = p[tid + 256];
    red[tid] = fmaxf(v0, v1); __syncthreads();
    for (int o = 128; o; o >>= 1) { if (tid < o) red[tid] = fmaxf(red[tid], red[tid + o]); __syncthreads(); }
    float m = red[0]; __syncthreads();
    float e0 = expf(v0 - m), e1 = expf(v1 - m);
    red[tid] = e0 + e1; __syncthreads();
    for (int o = 128; o; o >>= 1) { if (tid < o) red[tid] += red[tid + o]; __syncthreads(); }
    float inv = 1.f / red[0];
    p[tid] = e0 * inv; p[tid + 256] = e1 * inv;
}

// ------------- u[b,h,:] = sum_s attn * msg_g --------------------------------
__global__ __launch_bounds__(256) void u_kernel() {
    int b = blockIdx.x, ch = blockIdx.y, tid = threadIdx.x;
    __shared__ float aw[NH][64];
    for (int t = tid; t < NH * 64; t += 256) {
        int h = t >> 6, s = t & 63;
        aw[h][s] = g_attn[(b * NH + h) * SS + ch * 64 + s];
    }
    __syncthreads();
    int j0 = tid, j1 = tid + 256, j2 = tid + 512;
    float acc[NH][3];
#pragma unroll
    for (int h = 0; h < NH; h++) { acc[h][0] = acc[h][1] = acc[h][2] = 0.f; }
    for (int s = 0; s < 64; s++) {
        const float* mr = g_msgg + (size_t)(b * SS + ch * 64 + s) * HH;
        float x0 = mr[j0], x1 = mr[j1], x2 = mr[j2];
#pragma unroll
        for (int h = 0; h < NH; h++) {
            float w = aw[h][s];
            acc[h][0] = fmaf(w, x0, acc[h][0]);
            acc[h][1] = fmaf(w, x1, acc[h][1]);
            acc[h][2] = fmaf(w, x2, acc[h][2]);
        }
    }
#pragma unroll
    for (int h = 0; h < NH; h++) {
        atomicAdd(&g_u[(b * NH + h) * HH + j0], acc[h][0]);
        atomicAdd(&g_u[(b * NH + h) * HH + j1], acc[h][1]);
        atomicAdd(&g_u[(b * NH + h) * HH + j2], acc[h][2]);
    }
}

// ------------- ctx -> wo -> LN -> MLP -> out --------------------------------
__global__ __launch_bounds__(256) void final_kernel(
    const float* __restrict__ wv, const float* __restrict__ bv,
    const float* __restrict__ wo, const float* __restrict__ bo,
    const float* __restrict__ lng, const float* __restrict__ lnb,
    const float* __restrict__ f0w, const float* __restrict__ f0b,
    const float* __restrict__ f1w, const float* __restrict__ f1b,
    const float* __restrict__ f2w, const float* __restrict__ f2b,
    float* __restrict__ out)
{
    int b = blockIdx.x, tid = threadIdx.x;
    __shared__ float u_s[NH * HH];
    __shared__ float ctx[HH], f[HH];
    __shared__ float hb1[512], hb2[128];
    __shared__ float red[256];
    for (int t = tid; t < NH * HH; t += 256) u_s[t] = g_u[(size_t)b * NH * HH + t];
    __syncthreads();
    int j0 = tid, j1 = tid + 256, j2 = tid + 512;
    {   // ctx[o] = u[h(o),:] . wv[:,o] + bv[o]
        const float* u0 = u_s + (j0 / DHD) * HH;
        const float* u1 = u_s + (j1 / DHD) * HH;
        const float* u2 = u_s + (j2 / DHD) * HH;
        float a0 = bv[j0], a1 = bv[j1], a2 = bv[j2];
        for (int i = 0; i < HH; i++) {
            const float* w = wv + (size_t)i * HH;
            a0 = fmaf(u0[i], w[j0], a0);
            a1 = fmaf(u1[i], w[j1], a1);
            a2 = fmaf(u2[i], w[j2], a2);
        }
        ctx[j0] = a0; ctx[j1] = a1; ctx[j2] = a2;
    }
    __syncthreads();
    {   // y = ctx @ wo + bo + diff_g0
        float a0 = bo[j0], a1 = bo[j1], a2 = bo[j2];
        for (int i = 0; i < HH; i++) {
            float c = ctx[i]; const float* w = wo + (size_t)i * HH;
            a0 = fmaf(c, w[j0], a0); a1 = fmaf(c, w[j1], a1); a2 = fmaf(c, w[j2], a2);
        }
        f[j0] = a0 + g_diffg0[b * HH + j0];
        f[j1] = a1 + g_diffg0[b * HH + j1];
        f[j2] = a2 + g_diffg0[b * HH + j2];
    }
    __syncthreads();
    // LayerNorm
    red[tid] = f[j0] + f[j1] + f[j2]; __syncthreads();
    for (int o = 128; o; o >>= 1) { if (tid < o) red[tid] += red[tid + o]; __syncthreads(); }
    float mu = red[0] * (1.f / HH); __syncthreads();
    float d0 = f[j0] - mu, d1 = f[j1] - mu, d2 = f[j2] - mu;
    red[tid] = d0 * d0 + d1 * d1 + d2 * d2; __syncthreads();
    for (int o = 128; o; o >>= 1) { if (tid < o) red[tid] += red[tid + o]; __syncthreads(); }
    float rs = rsqrtf(red[0] * (1.f / HH) + 1e-5f); __syncthreads();
    f[j0] = d0 * rs * lng[j0] + lnb[j0];
    f[j1] = d1 * rs * lng[j1] + lnb[j1];
    f[j2] = d2 * rs * lng[j2] + lnb[j2];
    __syncthreads();
    // fc0: 768 -> 512, relu
    {
        int o0 = tid, o1 = tid + 256;
        float a0 = f0b[o0], a1 = f0b[o1];
        for (int i = 0; i < HH; i++) {
            float x = f[i]; const float* w = f0w + (size_t)i * 512;
            a0 = fmaf(x, w[o0], a0); a1 = fmaf(x, w[o1], a1);
        }
        hb1[o0] = a0 > 0.f ? a0 : 0.f;
        hb1[o1] = a1 > 0.f ? a1 : 0.f;
    }
    __syncthreads();
    // fc1: 512 -> 128, relu
    if (tid < 128) {
        float a = f1b[tid];
        for (int i = 0; i < 512; i++) a = fmaf(hb1[i], f1w[i * 128 + tid], a);
        hb2[tid] = a > 0.f ? a : 0.f;
    }
    __syncthreads();
    // fc2: 128 -> 2
    if (tid < 2) {
        float a = f2b[tid];
        for (int i = 0; i < 128; i++) a = fmaf(hb2[i], f2w[i * 2 + tid], a);
        out[b * 2 + tid] = a;
    }
}

extern "C" void kernel_launch(void* const* d_in, const int* in_sizes, int n_in,
                              void* d_out, int out_size) {
    const float* diff  = (const float*)d_in[0];
    const float* msg   = (const float*)d_in[1];
    const int*   mask  = (const int*)d_in[2];
    const int*   ei_d  = (const int*)d_in[3];
    const int*   ei_m  = (const int*)d_in[4];
    const float* wl    = (const float*)d_in[5];
    const float* bl    = (const float*)d_in[6];
    const float* wr    = (const float*)d_in[7];
    const float* br    = (const float*)d_in[8];
    const float* att   = (const float*)d_in[9];
    const float* gbias = (const float*)d_in[10];
    const float* wq    = (const float*)d_in[11];
    const float* bq    = (const float*)d_in[12];
    const float* wk    = (const float*)d_in[13];
    const float* wv    = (const float*)d_in[15];
    const float* bv    = (const float*)d_in[16];
    const float* wo    = (const float*)d_in[17];
    const float* bo    = (const float*)d_in[18];
    const float* lng   = (const float*)d_in[19];
    const float* lnb   = (const float*)d_in[20];
    const float* f0w   = (const float*)d_in[21];
    const float* f0b   = (const float*)d_in[22];
    const float* f1w   = (const float*)d_in[23];
    const float* f1b   = (const float*)d_in[24];
    const float* f2w   = (const float*)d_in[25];
    const float* f2b   = (const float*)d_in[26];
    float* out = (float*)d_out;

    // launch order puts the fused GEMM at index 5 so ncu (-s 5 -c 1) profiles it
    zero_kernel<<<768, 256>>>();                                       // 0
    count_kernel<<<512, 256>>>(ei_m);                                  // 1
    scan_kernel<<<BB, 512>>>();                                        // 2
    scatter_kernel<<<512, 256>>>(ei_m);                                // 3
    diff0_kernel<<<BB, 256>>>(diff, ei_d, wl, bl, wr, br, att, gbias); // 4
    gemm_fused_kernel<<<dim3(12, (BB * SS) / BM), 256>>>(msg, wl, wr, bl, br); // 5
    gat_node_kernel<<<dim3(SS, BB), 128>>>(att, gbias, msg);           // 6
    qr_kernel<<<BB, 256>>>(wq, bq, wk);                                // 7
    scores_kernel<<<dim3(SS, BB), 256>>>(mask);                        // 8
    softmax_kernel<<<BB * NH, 256>>>();                                // 9
    u_kernel<<<dim3(BB, 8), 256>>>();                                  // 10
    final_kernel<<<BB, 256>>>(wv, bv, wo, bo, lng, lnb,
                              f0w, f0b, f1w, f1b, f2w, f2b, out);      // 11
}

// round 5
// speedup vs baseline: 1.6332x; 1.1058x over previous
#include <cuda_runtime.h>
#include <cuda_bf16.h>
#include <math.h>

#define BB 32
#define SS 512
#define HH 768
#define EE 4096
#define NH 8
#define DHD 96
#define NEGV -1000000000.0f
#define CAPD 64

#define BM 128
#define BN 128
#define BKK 32

// ------------- scratch ------------------------------------------------------
__device__ float g_xl[BB * SS * HH];
__device__ float g_xr[BB * SS * HH];
__device__ float g_msgg[BB * SS * HH];
__device__ int   g_cnt[BB * SS];
__device__ int   g_off[BB * SS];
__device__ int   g_cur[BB * SS];
__device__ int   g_esrc[BB * EE];
__device__ float g_dxl[BB * CAPD * HH];
__device__ float g_diffg0[BB * HH];
__device__ float g_r[BB * NH * HH];
__device__ float g_attn[BB * NH * SS];
__device__ float g_u[BB * NH * HH];
__device__ __nv_bfloat16 g_a_bf[BB * SS * HH];     // msg in bf16 [m][k]
__device__ __nv_bfloat16 g_w_bf[2 * HH * HH];      // wl,wr in bf16 TRANSPOSED [n][k]

__global__ void zero_kernel() {
    int i = blockIdx.x * 256 + threadIdx.x;
    if (i < BB * SS) g_cnt[i] = 0;
    if (i < BB * NH * HH) g_u[i] = 0.f;
}

// ------------- fp32 -> bf16 converts ----------------------------------------
__global__ void convert_a_kernel(const float* __restrict__ A) {
    int idx = blockIdx.x * 256 + threadIdx.x;      // one float4 per thread
    float4 v = *(const float4*)(A + (size_t)idx * 4);
    __nv_bfloat162 lo = __floats2bfloat162_rn(v.x, v.y);
    __nv_bfloat162 hi = __floats2bfloat162_rn(v.z, v.w);
    *(__nv_bfloat162*)(g_a_bf + (size_t)idx * 4)     = lo;
    *(__nv_bfloat162*)(g_a_bf + (size_t)idx * 4 + 2) = hi;
}

__global__ void convert_w_kernel(const float* __restrict__ Wl, const float* __restrict__ Wr) {
    __shared__ float sm[32][33];
    const float* W = blockIdx.z ? Wr : Wl;
    __nv_bfloat16* Wt = g_w_bf + (size_t)blockIdx.z * HH * HH;
    int n0 = blockIdx.x * 32, k0 = blockIdx.y * 32;
    int c = threadIdx.x & 31, r0 = threadIdx.x >> 5;
    for (int r = r0; r < 32; r += 8)
        sm[r][c] = W[(size_t)(k0 + r) * HH + n0 + c];
    __syncthreads();
    for (int r = r0; r < 32; r += 8)
        Wt[(size_t)(n0 + r) * HH + k0 + c] = __float2bfloat16(sm[c][r]);
}

// ------------- helpers ------------------------------------------------------
__device__ __forceinline__ void mma_bf16(float c[4], const unsigned a[4], const unsigned b[2]) {
    asm volatile(
        "mma.sync.aligned.m16n8k16.row.col.f32.bf16.bf16.f32 "
        "{%0,%1,%2,%3}, {%4,%5,%6,%7}, {%8,%9}, {%0,%1,%2,%3};"
        : "+f"(c[0]), "+f"(c[1]), "+f"(c[2]), "+f"(c[3])
        : "r"(a[0]), "r"(a[1]), "r"(a[2]), "r"(a[3]), "r"(b[0]), "r"(b[1]));
}

// ------------- bf16 GEMM: {g_xl,g_xr} = msg @ {wl,wr} + {bl,br} --------------
// A: g_a_bf [m][k] bf16. W: g_w_bf [n][k] bf16 (transposed). f32 accumulate.
__global__ __launch_bounds__(256) void gemm_bf16_kernel(
    const float* __restrict__ bl, const float* __restrict__ br)
{
    const int K = HH, N = HH;
    int bx = blockIdx.x;
    int which = (bx >= 6);
    const __nv_bfloat16* Wt = g_w_bf + (size_t)which * HH * HH;
    const float* bias = which ? br : bl;
    float* C = which ? g_xr : g_xl;
    int bn = (which ? bx - 6 : bx) * BN;
    int bm = blockIdx.y * BM;

    __shared__ __nv_bfloat16 As[BM][40];
    __shared__ __nv_bfloat16 Bs[BN][40];
    int tid = threadIdx.x;
    int wid = tid >> 5, lane = tid & 31;
    int wm = wid >> 2, wn = wid & 3;
    int g = lane >> 2, c2 = (lane & 3) << 1;

    float acc[4][4][4];
#pragma unroll
    for (int i = 0; i < 4; i++)
#pragma unroll
        for (int j = 0; j < 4; j++)
#pragma unroll
            for (int t = 0; t < 4; t++) acc[i][j][t] = 0.f;

    int lrow = tid >> 2;             // 0..63
    int lkq  = (tid & 3) << 3;       // 0,8,16,24 (bf16 units)

    uint4 av0, av1, bv0, bv1;
    av0 = *(const uint4*)(g_a_bf + (size_t)(bm + lrow) * K + lkq);
    av1 = *(const uint4*)(g_a_bf + (size_t)(bm + 64 + lrow) * K + lkq);
    bv0 = *(const uint4*)(Wt + (size_t)(bn + lrow) * K + lkq);
    bv1 = *(const uint4*)(Wt + (size_t)(bn + 64 + lrow) * K + lkq);

    for (int kt = 0; kt < K; kt += BKK) {
        *(uint4*)&As[lrow][lkq]      = av0;
        *(uint4*)&As[lrow + 64][lkq] = av1;
        *(uint4*)&Bs[lrow][lkq]      = bv0;
        *(uint4*)&Bs[lrow + 64][lkq] = bv1;
        __syncthreads();
        if (kt + BKK < K) {   // prefetch next slab
            av0 = *(const uint4*)(g_a_bf + (size_t)(bm + lrow) * K + kt + BKK + lkq);
            av1 = *(const uint4*)(g_a_bf + (size_t)(bm + 64 + lrow) * K + kt + BKK + lkq);
            bv0 = *(const uint4*)(Wt + (size_t)(bn + lrow) * K + kt + BKK + lkq);
            bv1 = *(const uint4*)(Wt + (size_t)(bn + 64 + lrow) * K + kt + BKK + lkq);
        }
#pragma unroll
        for (int ks = 0; ks < 2; ks++) {
            int k0 = ks << 4;
            unsigned af[4][4], bf[4][2];
#pragma unroll
            for (int i = 0; i < 4; i++) {
                int r = wm * 64 + i * 16;
                af[i][0] = *(const unsigned*)&As[r + g][k0 + c2];
                af[i][1] = *(const unsigned*)&As[r + 8 + g][k0 + c2];
                af[i][2] = *(const unsigned*)&As[r + g][k0 + 8 + c2];
                af[i][3] = *(const unsigned*)&As[r + 8 + g][k0 + 8 + c2];
            }
#pragma unroll
            for (int j = 0; j < 4; j++) {
                int n0 = wn * 32 + j * 8;
                bf[j][0] = *(const unsigned*)&Bs[n0 + g][k0 + c2];
                bf[j][1] = *(const unsigned*)&Bs[n0 + g][k0 + 8 + c2];
            }
#pragma unroll
            for (int i = 0; i < 4; i++)
#pragma unroll
                for (int j = 0; j < 4; j++)
                    mma_bf16(acc[i][j], af[i], bf[j]);
        }
        __syncthreads();
    }

#pragma unroll
    for (int i = 0; i < 4; i++) {
#pragma unroll
        for (int j = 0; j < 4; j++) {
            int row = bm + wm * 64 + i * 16 + g;
            int col = bn + wn * 32 + j * 8 + c2;
            float b0 = bias[col], b1 = bias[col + 1];
            float2 o0 = make_float2(acc[i][j][0] + b0, acc[i][j][1] + b1);
            float2 o1 = make_float2(acc[i][j][2] + b0, acc[i][j][3] + b1);
            *(float2*)(C + (size_t)row * N + col) = o0;
            *(float2*)(C + (size_t)(row + 8) * N + col) = o1;
        }
    }
}

// ------------- CSR build ----------------------------------------------------
__global__ void count_kernel(const int* __restrict__ ei) {
    int idx = blockIdx.x * 256 + threadIdx.x;
    if (idx >= BB * EE) return;
    int b = idx >> 12, e = idx & 4095;
    int s = ei[b * 2 * EE + e], d = ei[b * 2 * EE + EE + e];
    if ((unsigned)s < SS && (unsigned)d < SS) atomicAdd(&g_cnt[b * SS + d], 1);
}

__global__ void scan_kernel() {
    int b = blockIdx.x, tid = threadIdx.x;
    __shared__ int sc[SS];
    int c = g_cnt[b * SS + tid];
    sc[tid] = c;
    __syncthreads();
    for (int off = 1; off < SS; off <<= 1) {
        int t = (tid >= off) ? sc[tid - off] : 0;
        __syncthreads();
        sc[tid] += t;
        __syncthreads();
    }
    int ex = sc[tid] - c;
    g_off[b * SS + tid] = ex;
    g_cur[b * SS + tid] = ex;
}

__global__ void scatter_kernel(const int* __restrict__ ei) {
    int idx = blockIdx.x * 256 + threadIdx.x;
    if (idx >= BB * EE) return;
    int b = idx >> 12, e = idx & 4095;
    int s = ei[b * 2 * EE + e], d = ei[b * 2 * EE + EE + e];
    if ((unsigned)s < SS && (unsigned)d < SS) {
        int p = atomicAdd(&g_cur[b * SS + d], 1);
        g_esrc[b * EE + p] = s;
    }
}

// ------------- msg GAT: one-pass online softmax per dst node -----------------
__global__ __launch_bounds__(128) void gat_node_kernel(
    const float* __restrict__ att, const float* __restrict__ gbias,
    const float* __restrict__ msg)
{
    int n = blockIdx.x, b = blockIdx.y, tid = threadIdx.x;
    int node = b * SS + n;
    __shared__ float red[4];
    int warp = tid >> 5, lane = tid & 31;

    float xr_r[6], att_r[6], acc[6];
#pragma unroll
    for (int j = 0; j < 6; j++) {
        int h = tid + 128 * j;
        xr_r[j]  = g_xr[(size_t)node * HH + h];
        att_r[j] = att[h];
        acc[j] = 0.f;
    }
    int deg = g_cnt[node];
    int base = b * EE + g_off[node];
    float m = -3.4e38f, ssum = 0.f;

    for (int i = 0; i <= deg; i++) {
        int src = (i < deg) ? g_esrc[base + i] : n;   // self-loop last
        const float* row = g_xl + (size_t)(b * SS + src) * HH;
        float vj[6], part = 0.f;
#pragma unroll
        for (int j = 0; j < 6; j++) {
            float v = row[tid + 128 * j];
            vj[j] = v;
            float z = v + xr_r[j];
            z = z > 0.f ? z : 0.2f * z;
            part = fmaf(z, att_r[j], part);
        }
#pragma unroll
        for (int o = 16; o; o >>= 1) part += __shfl_xor_sync(0xffffffffu, part, o);
        if (lane == 0) red[warp] = part;
        __syncthreads();
        float e = red[0] + red[1] + red[2] + red[3];
        __syncthreads();
        float mn = fmaxf(m, e);
        float scale = __expf(m - mn);
        float p = __expf(e - mn);
        ssum = ssum * scale + p;
#pragma unroll
        for (int j = 0; j < 6; j++) acc[j] = fmaf(acc[j], scale, p * vj[j]);
        m = mn;
    }
    float inv = 1.f / ssum;
#pragma unroll
    for (int j = 0; j < 6; j++) {
        int h = tid + 128 * j;
        g_msgg[(size_t)node * HH + h] = acc[j] * inv + gbias[h] + msg[(size_t)node * HH + h];
    }
}

// ------------- diff GAT at node 0 only (per batch) --------------------------
__global__ __launch_bounds__(256) void diff0_kernel(
    const float* __restrict__ diff, const int* __restrict__ ei,
    const float* __restrict__ wl, const float* __restrict__ bl,
    const float* __restrict__ wr, const float* __restrict__ br,
    const float* __restrict__ att, const float* __restrict__ gbias)
{
    int b = blockIdx.x, tid = threadIdx.x;
    __shared__ float xrows[8][HH];
    __shared__ float xr0[HH], x0s[HH];
    __shared__ float evals[CAPD];
    __shared__ int srcs[CAPD];
    __shared__ float red[256];
    __shared__ int scnt;
    if (tid == 0) scnt = 0;
    const float* x0 = diff + (size_t)b * SS * HH;
    for (int j = tid; j < HH; j += 256) x0s[j] = x0[j];
    __syncthreads();
    int j0 = tid, j1 = tid + 256, j2 = tid + 512;
    {   // xr0 = x0 @ wr + br
        float a0 = br[j0], a1 = br[j1], a2 = br[j2];
        for (int i = 0; i < HH; i++) {
            float x = x0s[i]; const float* w = wr + (size_t)i * HH;
            a0 = fmaf(x, w[j0], a0); a1 = fmaf(x, w[j1], a1); a2 = fmaf(x, w[j2], a2);
        }
        xr0[j0] = a0; xr0[j1] = a1; xr0[j2] = a2;
    }
    for (int e = tid; e < EE; e += 256) {
        int s = ei[b * 2 * EE + e], dd = ei[b * 2 * EE + EE + e];
        if ((unsigned)s < SS && dd == 0) {
            int p = atomicAdd(&scnt, 1);
            if (p < CAPD - 1) srcs[p] = s;
        }
    }
    __syncthreads();
    int nd = min(scnt, CAPD - 1);
    if (tid == 0) srcs[nd] = 0;
    __syncthreads();
    int d = nd + 1;

    for (int c0 = 0; c0 < d; c0 += 8) {
        int nc = min(8, d - c0);
        for (int t = tid; t < nc * HH; t += 256) {
            int s = t / HH, j = t - s * HH;
            xrows[s][j] = diff[((size_t)b * SS + srcs[c0 + s]) * HH + j];
        }
        __syncthreads();
        float acc[8][3];
#pragma unroll
        for (int s = 0; s < 8; s++) { acc[s][0] = bl[j0]; acc[s][1] = bl[j1]; acc[s][2] = bl[j2]; }
        for (int i = 0; i < HH; i++) {
            const float* w = wl + (size_t)i * HH;
            float w0 = w[j0], w1 = w[j1], w2 = w[j2];
#pragma unroll
            for (int s = 0; s < 8; s++) {
                float x = xrows[s][i];
                acc[s][0] = fmaf(x, w0, acc[s][0]);
                acc[s][1] = fmaf(x, w1, acc[s][1]);
                acc[s][2] = fmaf(x, w2, acc[s][2]);
            }
        }
        for (int s = 0; s < nc; s++) {
            float* xp = g_dxl + ((size_t)b * CAPD + c0 + s) * HH;
            xp[j0] = acc[s][0]; xp[j1] = acc[s][1]; xp[j2] = acc[s][2];
            float z0 = acc[s][0] + xr0[j0]; z0 = z0 > 0.f ? z0 : 0.2f * z0;
            float z1 = acc[s][1] + xr0[j1]; z1 = z1 > 0.f ? z1 : 0.2f * z1;
            float z2 = acc[s][2] + xr0[j2]; z2 = z2 > 0.f ? z2 : 0.2f * z2;
            red[tid] = z0 * att[j0] + z1 * att[j1] + z2 * att[j2];
            __syncthreads();
            for (int o = 128; o; o >>= 1) { if (tid < o) red[tid] += red[tid + o]; __syncthreads(); }
            if (tid == 0) evals[c0 + s] = red[0];
            __syncthreads();
        }
    }
    float m = -3.4e38f;
    for (int i = tid; i < d; i += 256) m = fmaxf(m, evals[i]);
    red[tid] = m; __syncthreads();
    for (int o = 128; o; o >>= 1) { if (tid < o) red[tid] = fmaxf(red[tid], red[tid + o]); __syncthreads(); }
    float emax = red[0]; __syncthreads();
    float ssum = 0.f;
    for (int i = tid; i < d; i += 256) { float p = expf(evals[i] - emax); evals[i] = p; ssum += p; }
    red[tid] = ssum; __syncthreads();
    for (int o = 128; o; o >>= 1) { if (tid < o) red[tid] += red[tid + o]; __syncthreads(); }
    float inv = 1.f / red[0];
    __syncthreads();
    float o0 = 0.f, o1 = 0.f, o2 = 0.f;
    for (int s = 0; s < d; s++) {
        const float* xp = g_dxl + ((size_t)b * CAPD + s) * HH;
        float al = evals[s] * inv;
        o0 = fmaf(al, xp[j0], o0);
        o1 = fmaf(al, xp[j1], o1);
        o2 = fmaf(al, xp[j2], o2);
    }
    g_diffg0[b * HH + j0] = o0 + gbias[j0] + x0s[j0];
    g_diffg0[b * HH + j1] = o1 + gbias[j1] + x0s[j1];
    g_diffg0[b * HH + j2] = o2 + gbias[j2] + x0s[j2];
}

// ------------- q0 and folded r ----------------------------------------------
__global__ __launch_bounds__(256) void qr_kernel(
    const float* __restrict__ wq, const float* __restrict__ bq,
    const float* __restrict__ wk)
{
    int b = blockIdx.x, tid = threadIdx.x;
    __shared__ float x[HH], q0[HH];
    for (int j = tid; j < HH; j += 256) x[j] = g_diffg0[b * HH + j];
    __syncthreads();
    int j0 = tid, j1 = tid + 256, j2 = tid + 512;
    {
        float a0 = bq[j0], a1 = bq[j1], a2 = bq[j2];
        for (int i = 0; i < HH; i++) {
            float xv = x[i]; const float* w = wq + (size_t)i * HH;
            a0 = fmaf(xv, w[j0], a0); a1 = fmaf(xv, w[j1], a1); a2 = fmaf(xv, w[j2], a2);
        }
        q0[j0] = a0; q0[j1] = a1; q0[j2] = a2;
    }
    __syncthreads();
    const float RS = 0.10206207261596577f;  // 1/sqrt(96)
    for (int t = tid; t < NH * HH; t += 256) {
        int h = t / HH, i = t - h * HH;
        const float4* wp = (const float4*)(wk + (size_t)i * HH + h * DHD);
        const float4* qp = (const float4*)(q0 + h * DHD);
        float s = 0.f;
#pragma unroll
        for (int d4 = 0; d4 < DHD / 4; d4++) {
            float4 w4 = wp[d4]; float4 q4 = qp[d4];
            s = fmaf(w4.x, q4.x, s); s = fmaf(w4.y, q4.y, s);
            s = fmaf(w4.z, q4.z, s); s = fmaf(w4.w, q4.w, s);
        }
        g_r[(b * NH + h) * HH + i] = s * RS;
    }
}

// ------------- scores -------------------------------------------------------
__global__ __launch_bounds__(256) void scores_kernel(const int* __restrict__ mask) {
    int s = blockIdx.x, b = blockIdx.y, tid = threadIdx.x;
    __shared__ float row[HH];
    for (int j = tid; j < HH; j += 256) row[j] = g_msgg[(size_t)(b * SS + s) * HH + j];
    __syncthreads();
    int warp = tid >> 5, lane = tid & 31;   // warp == head
    const float* rp = g_r + (size_t)(b * NH + warp) * HH;
    float acc = 0.f;
    for (int j = lane; j < HH; j += 32) acc = fmaf(rp[j], row[j], acc);
#pragma unroll
    for (int o = 16; o; o >>= 1) acc += __shfl_xor_sync(0xffffffffu, acc, o);
    if (lane == 0)
        g_attn[(b * NH + warp) * SS + s] = (mask[b * SS + s] == 0) ? NEGV : acc;
}

__global__ __launch_bounds__(256) void softmax_kernel() {
    int bh = blockIdx.x, tid = threadIdx.x;
    __shared__ float red[256];
    float* p = g_attn + (size_t)bh * SS;
    float v0 = p[tid], v1 = p[tid + 256];
    red[tid] = fmaxf(v0, v1); __syncthreads();
    for (int o = 128; o; o >>= 1) { if (tid < o) red[tid] = fmaxf(red[tid], red[tid + o]); __syncthreads(); }
    float m = red[0]; __syncthreads();
    float e0 = expf(v0 - m), e1 = expf(v1 - m);
    red[tid] = e0 + e1; __syncthreads();
    for (int o = 128; o; o >>= 1) { if (tid < o) red[tid] += red[tid + o]; __syncthreads(); }
    float inv = 1.f / red[0];
    p[tid] = e0 * inv; p[tid + 256] = e1 * inv;
}

// ------------- u[b,h,:] = sum_s attn * msg_g --------------------------------
__global__ __launch_bounds__(256) void u_kernel() {
    int b = blockIdx.x, ch = blockIdx.y, tid = threadIdx.x;
    __shared__ float aw[NH][64];
    for (int t = tid; t < NH * 64; t += 256) {
        int h = t >> 6, s = t & 63;
        aw[h][s] = g_attn[(b * NH + h) * SS + ch * 64 + s];
    }
    __syncthreads();
    int j0 = tid, j1 = tid + 256, j2 = tid + 512;
    float acc[NH][3];
#pragma unroll
    for (int h = 0; h < NH; h++) { acc[h][0] = acc[h][1] = acc[h][2] = 0.f; }
    for (int s = 0; s < 64; s++) {
        const float* mr = g_msgg + (size_t)(b * SS + ch * 64 + s) * HH;
        float x0 = mr[j0], x1 = mr[j1], x2 = mr[j2];
#pragma unroll
        for (int h = 0; h < NH; h++) {
            float w = aw[h][s];
            acc[h][0] = fmaf(w, x0, acc[h][0]);
            acc[h][1] = fmaf(w, x1, acc[h][1]);
            acc[h][2] = fmaf(w, x2, acc[h][2]);
        }
    }
#pragma unroll
    for (int h = 0; h < NH; h++) {
        atomicAdd(&g_u[(b * NH + h) * HH + j0], acc[h][0]);
        atomicAdd(&g_u[(b * NH + h) * HH + j1], acc[h][1]);
        atomicAdd(&g_u[(b * NH + h) * HH + j2], acc[h][2]);
    }
}

// ------------- ctx -> wo -> LN -> MLP -> out --------------------------------
__global__ __launch_bounds__(256) void final_kernel(
    const float* __restrict__ wv, const float* __restrict__ bv,
    const float* __restrict__ wo, const float* __restrict__ bo,
    const float* __restrict__ lng, const float* __restrict__ lnb,
    const float* __restrict__ f0w, const float* __restrict__ f0b,
    const float* __restrict__ f1w, const float* __restrict__ f1b,
    const float* __restrict__ f2w, const float* __restrict__ f2b,
    float* __restrict__ out)
{
    int b = blockIdx.x, tid = threadIdx.x;
    __shared__ float u_s[NH * HH];
    __shared__ float ctx[HH], f[HH];
    __shared__ float hb1[512], hb2[128];
    __shared__ float red[256];
    for (int t = tid; t < NH * HH; t += 256) u_s[t] = g_u[(size_t)b * NH * HH + t];
    __syncthreads();
    int j0 = tid, j1 = tid + 256, j2 = tid + 512;
    {   // ctx[o] = u[h(o),:] . wv[:,o] + bv[o]
        const float* u0 = u_s + (j0 / DHD) * HH;
        const float* u1 = u_s + (j1 / DHD) * HH;
        const float* u2 = u_s + (j2 / DHD) * HH;
        float a0 = bv[j0], a1 = bv[j1], a2 = bv[j2];
        for (int i = 0; i < HH; i++) {
            const float* w = wv + (size_t)i * HH;
            a0 = fmaf(u0[i], w[j0], a0);
            a1 = fmaf(u1[i], w[j1], a1);
            a2 = fmaf(u2[i], w[j2], a2);
        }
        ctx[j0] = a0; ctx[j1] = a1; ctx[j2] = a2;
    }
    __syncthreads();
    {   // y = ctx @ wo + bo + diff_g0
        float a0 = bo[j0], a1 = bo[j1], a2 = bo[j2];
        for (int i = 0; i < HH; i++) {
            float c = ctx[i]; const float* w = wo + (size_t)i * HH;
            a0 = fmaf(c, w[j0], a0); a1 = fmaf(c, w[j1], a1); a2 = fmaf(c, w[j2], a2);
        }
        f[j0] = a0 + g_diffg0[b * HH + j0];
        f[j1] = a1 + g_diffg0[b * HH + j1];
        f[j2] = a2 + g_diffg0[b * HH + j2];
    }
    __syncthreads();
    // LayerNorm
    red[tid] = f[j0] + f[j1] + f[j2]; __syncthreads();
    for (int o = 128; o; o >>= 1) { if (tid < o) red[tid] += red[tid + o]; __syncthreads(); }
    float mu = red[0] * (1.f / HH); __syncthreads();
    float d0 = f[j0] - mu, d1 = f[j1] - mu, d2 = f[j2] - mu;
    red[tid] = d0 * d0 + d1 * d1 + d2 * d2; __syncthreads();
    for (int o = 128; o; o >>= 1) { if (tid < o) red[tid] += red[tid + o]; __syncthreads(); }
    float rs = rsqrtf(red[0] * (1.f / HH) + 1e-5f); __syncthreads();
    f[j0] = d0 * rs * lng[j0] + lnb[j0];
    f[j1] = d1 * rs * lng[j1] + lnb[j1];
    f[j2] = d2 * rs * lng[j2] + lnb[j2];
    __syncthreads();
    // fc0: 768 -> 512, relu
    {
        int o0 = tid, o1 = tid + 256;
        float a0 = f0b[o0], a1 = f0b[o1];
        for (int i = 0; i < HH; i++) {
            float x = f[i]; const float* w = f0w + (size_t)i * 512;
            a0 = fmaf(x, w[o0], a0); a1 = fmaf(x, w[o1], a1);
        }
        hb1[o0] = a0 > 0.f ? a0 : 0.f;
        hb1[o1] = a1 > 0.f ? a1 : 0.f;
    }
    __syncthreads();
    // fc1: 512 -> 128, relu
    if (tid < 128) {
        float a = f1b[tid];
        for (int i = 0; i < 512; i++) a = fmaf(hb1[i], f1w[i * 128 + tid], a);
        hb2[tid] = a > 0.f ? a : 0.f;
    }
    __syncthreads();
    // fc2: 128 -> 2
    if (tid < 2) {
        float a = f2b[tid];
        for (int i = 0; i < 128; i++) a = fmaf(hb2[i], f2w[i * 2 + tid], a);
        out[b * 2 + tid] = a;
    }
}

extern "C" void kernel_launch(void* const* d_in, const int* in_sizes, int n_in,
                              void* d_out, int out_size) {
    const float* diff  = (const float*)d_in[0];
    const float* msg   = (const float*)d_in[1];
    const int*   mask  = (const int*)d_in[2];
    const int*   ei_d  = (const int*)d_in[3];
    const int*   ei_m  = (const int*)d_in[4];
    const float* wl    = (const float*)d_in[5];
    const float* bl    = (const float*)d_in[6];
    const float* wr    = (const float*)d_in[7];
    const float* br    = (const float*)d_in[8];
    const float* att   = (const float*)d_in[9];
    const float* gbias = (const float*)d_in[10];
    const float* wq    = (const float*)d_in[11];
    const float* bq    = (const float*)d_in[12];
    const float* wk    = (const float*)d_in[13];
    const float* wv    = (const float*)d_in[15];
    const float* bv    = (const float*)d_in[16];
    const float* wo    = (const float*)d_in[17];
    const float* bo    = (const float*)d_in[18];
    const float* lng   = (const float*)d_in[19];
    const float* lnb   = (const float*)d_in[20];
    const float* f0w   = (const float*)d_in[21];
    const float* f0b   = (const float*)d_in[22];
    const float* f1w   = (const float*)d_in[23];
    const float* f1b   = (const float*)d_in[24];
    const float* f2w   = (const float*)d_in[25];
    const float* f2b   = (const float*)d_in[26];
    float* out = (float*)d_out;

    // index 3 (mine) == skip-5 target of ncu (harness pre-launches 2)
    zero_kernel<<<768, 256>>>();                                        // 0
    convert_a_kernel<<<BB * SS * HH / 1024, 256>>>(msg);                // 1
    convert_w_kernel<<<dim3(HH / 32, HH / 32, 2), 256>>>(wl, wr);       // 2
    gemm_bf16_kernel<<<dim3(12, (BB * SS) / BM), 256>>>(bl, br);        // 3  <- ncu
    count_kernel<<<512, 256>>>(ei_m);                                   // 4
    scan_kernel<<<BB, 512>>>();                                         // 5
    scatter_kernel<<<512, 256>>>(ei_m);                                 // 6
    diff0_kernel<<<BB, 256>>>(diff, ei_d, wl, bl, wr, br, att, gbias);  // 7
    gat_node_kernel<<<dim3(SS, BB), 128>>>(att, gbias, msg);            // 8
    qr_kernel<<<BB, 256>>>(wq, bq, wk);                                 // 9
    scores_kernel<<<dim3(SS, BB), 256>>>(mask);                         // 10
    softmax_kernel<<<BB * NH, 256>>>();                                 // 11
    u_kernel<<<dim3(BB, 8), 256>>>();                                   // 12
    final_kernel<<<BB, 256>>>(wv, bv, wo, bo, lng, lnb,
                              f0w, f0b, f1w, f1b, f2w, f2b, out);       // 13
}

// round 6
// speedup vs baseline: 2.0784x; 1.2726x over previous
#include <cuda_runtime.h>
#include <cuda_bf16.h>
#include <math.h>

#define BB 32
#define SS 512
#define HH 768
#define EE 4096
#define NH 8
#define DHD 96
#define NEGV -1000000000.0f
#define CAPD 64

#define BM 128
#define BN 128
#define BKK 32

// ------------- scratch ------------------------------------------------------
__device__ __nv_bfloat16 g_xlbf[BB * SS * HH];
__device__ __nv_bfloat16 g_xrbf[BB * SS * HH];
__device__ float g_msgg[BB * SS * HH];
__device__ int   g_cnt[BB * SS];
__device__ int   g_off[BB * SS];
__device__ int   g_cur[BB * SS];
__device__ int   g_esrc[BB * EE];
__device__ int   g_src0[BB * CAPD];
__device__ int   g_nd[BB];
__device__ float g_dxl[BB * CAPD * HH];
__device__ float g_xr0[BB * HH];
__device__ float g_diffg0[BB * HH];
__device__ float g_q0[BB * HH];
__device__ float g_r[BB * NH * HH];
__device__ float g_attn[BB * NH * SS];
__device__ float g_u[BB * NH * HH];
__device__ float g_ctx[BB * HH];
__device__ float g_f[BB * HH];
__device__ float g_fln[BB * HH];
__device__ float g_h1[BB * 512];
__device__ __nv_bfloat16 g_a_bf[BB * SS * HH];
__device__ __nv_bfloat16 g_w_bf[2 * HH * HH];

__global__ void zero_kernel() {
    int i = blockIdx.x * 256 + threadIdx.x;
    if (i < BB * SS) g_cnt[i] = 0;
    if (i < BB * NH * HH) g_u[i] = 0.f;
}

// ------------- fp32 -> bf16 converts ----------------------------------------
__global__ void convert_a_kernel(const float* __restrict__ A) {
    int idx = blockIdx.x * 256 + threadIdx.x;
    float4 v = *(const float4*)(A + (size_t)idx * 4);
    *(__nv_bfloat162*)(g_a_bf + (size_t)idx * 4)     = __floats2bfloat162_rn(v.x, v.y);
    *(__nv_bfloat162*)(g_a_bf + (size_t)idx * 4 + 2) = __floats2bfloat162_rn(v.z, v.w);
}

__global__ void convert_w_kernel(const float* __restrict__ Wl, const float* __restrict__ Wr) {
    __shared__ float sm[32][33];
    const float* W = blockIdx.z ? Wr : Wl;
    __nv_bfloat16* Wt = g_w_bf + (size_t)blockIdx.z * HH * HH;
    int n0 = blockIdx.x * 32, k0 = blockIdx.y * 32;
    int c = threadIdx.x & 31, r0 = threadIdx.x >> 5;
    for (int r = r0; r < 32; r += 8)
        sm[r][c] = W[(size_t)(k0 + r) * HH + n0 + c];
    __syncthreads();
    for (int r = r0; r < 32; r += 8)
        Wt[(size_t)(n0 + r) * HH + k0 + c] = __float2bfloat16(sm[c][r]);
}

// ------------- helpers ------------------------------------------------------
__device__ __forceinline__ void mma_bf16(float c[4], const unsigned a[4], const unsigned b[2]) {
    asm volatile(
        "mma.sync.aligned.m16n8k16.row.col.f32.bf16.bf16.f32 "
        "{%0,%1,%2,%3}, {%4,%5,%6,%7}, {%8,%9}, {%0,%1,%2,%3};"
        : "+f"(c[0]), "+f"(c[1]), "+f"(c[2]), "+f"(c[3])
        : "r"(a[0]), "r"(a[1]), "r"(a[2]), "r"(a[3]), "r"(b[0]), "r"(b[1]));
}

// ------------- bf16 GEMM -> bf16 outputs g_xlbf/g_xrbf -----------------------
__global__ __launch_bounds__(256) void gemm_bf16_kernel(
    const float* __restrict__ bl, const float* __restrict__ br)
{
    const int K = HH, N = HH;
    int bx = blockIdx.x;
    int which = (bx >= 6);
    const __nv_bfloat16* Wt = g_w_bf + (size_t)which * HH * HH;
    const float* bias = which ? br : bl;
    __nv_bfloat16* C = which ? g_xrbf : g_xlbf;
    int bn = (which ? bx - 6 : bx) * BN;
    int bm = blockIdx.y * BM;

    __shared__ __nv_bfloat16 As[BM][40];
    __shared__ __nv_bfloat16 Bs[BN][40];
    int tid = threadIdx.x;
    int wid = tid >> 5, lane = tid & 31;
    int wm = wid >> 2, wn = wid & 3;
    int g = lane >> 2, c2 = (lane & 3) << 1;

    float acc[4][4][4];
#pragma unroll
    for (int i = 0; i < 4; i++)
#pragma unroll
        for (int j = 0; j < 4; j++)
#pragma unroll
            for (int t = 0; t < 4; t++) acc[i][j][t] = 0.f;

    int lrow = tid >> 2;
    int lkq  = (tid & 3) << 3;

    uint4 av0, av1, bv0, bv1;
    av0 = *(const uint4*)(g_a_bf + (size_t)(bm + lrow) * K + lkq);
    av1 = *(const uint4*)(g_a_bf + (size_t)(bm + 64 + lrow) * K + lkq);
    bv0 = *(const uint4*)(Wt + (size_t)(bn + lrow) * K + lkq);
    bv1 = *(const uint4*)(Wt + (size_t)(bn + 64 + lrow) * K + lkq);

    for (int kt = 0; kt < K; kt += BKK) {
        *(uint4*)&As[lrow][lkq]      = av0;
        *(uint4*)&As[lrow + 64][lkq] = av1;
        *(uint4*)&Bs[lrow][lkq]      = bv0;
        *(uint4*)&Bs[lrow + 64][lkq] = bv1;
        __syncthreads();
        if (kt + BKK < K) {
            av0 = *(const uint4*)(g_a_bf + (size_t)(bm + lrow) * K + kt + BKK + lkq);
            av1 = *(const uint4*)(g_a_bf + (size_t)(bm + 64 + lrow) * K + kt + BKK + lkq);
            bv0 = *(const uint4*)(Wt + (size_t)(bn + lrow) * K + kt + BKK + lkq);
            bv1 = *(const uint4*)(Wt + (size_t)(bn + 64 + lrow) * K + kt + BKK + lkq);
        }
#pragma unroll
        for (int ks = 0; ks < 2; ks++) {
            int k0 = ks << 4;
            unsigned af[4][4], bf[4][2];
#pragma unroll
            for (int i = 0; i < 4; i++) {
                int r = wm * 64 + i * 16;
                af[i][0] = *(const unsigned*)&As[r + g][k0 + c2];
                af[i][1] = *(const unsigned*)&As[r + 8 + g][k0 + c2];
                af[i][2] = *(const unsigned*)&As[r + g][k0 + 8 + c2];
                af[i][3] = *(const unsigned*)&As[r + 8 + g][k0 + 8 + c2];
            }
#pragma unroll
            for (int j = 0; j < 4; j++) {
                int n0 = wn * 32 + j * 8;
                bf[j][0] = *(const unsigned*)&Bs[n0 + g][k0 + c2];
                bf[j][1] = *(const unsigned*)&Bs[n0 + g][k0 + 8 + c2];
            }
#pragma unroll
            for (int i = 0; i < 4; i++)
#pragma unroll
                for (int j = 0; j < 4; j++)
                    mma_bf16(acc[i][j], af[i], bf[j]);
        }
        __syncthreads();
    }

#pragma unroll
    for (int i = 0; i < 4; i++) {
#pragma unroll
        for (int j = 0; j < 4; j++) {
            int row = bm + wm * 64 + i * 16 + g;
            int col = bn + wn * 32 + j * 8 + c2;
            float b0 = bias[col], b1 = bias[col + 1];
            *(__nv_bfloat162*)(C + (size_t)row * N + col) =
                __floats2bfloat162_rn(acc[i][j][0] + b0, acc[i][j][1] + b1);
            *(__nv_bfloat162*)(C + (size_t)(row + 8) * N + col) =
                __floats2bfloat162_rn(acc[i][j][2] + b0, acc[i][j][3] + b1);
        }
    }
}

// ------------- CSR build ----------------------------------------------------
__global__ void count_kernel(const int* __restrict__ ei) {
    int idx = blockIdx.x * 256 + threadIdx.x;
    if (idx >= BB * EE) return;
    int b = idx >> 12, e = idx & 4095;
    int s = ei[b * 2 * EE + e], d = ei[b * 2 * EE + EE + e];
    if ((unsigned)s < SS && (unsigned)d < SS) atomicAdd(&g_cnt[b * SS + d], 1);
}

__global__ void scan_kernel() {
    int b = blockIdx.x, tid = threadIdx.x;
    __shared__ int sc[SS];
    int c = g_cnt[b * SS + tid];
    sc[tid] = c;
    __syncthreads();
    for (int off = 1; off < SS; off <<= 1) {
        int t = (tid >= off) ? sc[tid - off] : 0;
        __syncthreads();
        sc[tid] += t;
        __syncthreads();
    }
    int ex = sc[tid] - c;
    g_off[b * SS + tid] = ex;
    g_cur[b * SS + tid] = ex;
}

__global__ void scatter_kernel(const int* __restrict__ ei) {
    int idx = blockIdx.x * 256 + threadIdx.x;
    if (idx >= BB * EE) return;
    int b = idx >> 12, e = idx & 4095;
    int s = ei[b * 2 * EE + e], d = ei[b * 2 * EE + EE + e];
    if ((unsigned)s < SS && (unsigned)d < SS) {
        int p = atomicAdd(&g_cur[b * SS + d], 1);
        g_esrc[b * EE + p] = s;
    }
}

// ------------- msg GAT: one-pass online softmax, bf16 rows -------------------
__global__ __launch_bounds__(128) void gat_node_kernel(
    const float* __restrict__ att, const float* __restrict__ gbias,
    const float* __restrict__ msg)
{
    int n = blockIdx.x, b = blockIdx.y, tid = threadIdx.x;
    int node = b * SS + n;
    __shared__ float red[4];
    int warp = tid >> 5, lane = tid & 31;

    const __nv_bfloat162* xrp = (const __nv_bfloat162*)(g_xrbf + (size_t)node * HH);
    float2 xr_r[3], att_r[3], acc[3];
#pragma unroll
    for (int j = 0; j < 3; j++) {
        int p = tid + 128 * j;
        xr_r[j]  = __bfloat1622float2(xrp[p]);
        att_r[j] = *(const float2*)(att + 2 * p);
        acc[j] = make_float2(0.f, 0.f);
    }
    int deg = g_cnt[node];
    int base = b * EE + g_off[node];
    float m = -3.4e38f, ssum = 0.f;

    for (int i = 0; i <= deg; i++) {
        int src = (i < deg) ? g_esrc[base + i] : n;
        const __nv_bfloat162* rowp = (const __nv_bfloat162*)(g_xlbf + (size_t)(b * SS + src) * HH);
        float2 vj[3];
        float part = 0.f;
#pragma unroll
        for (int j = 0; j < 3; j++) {
            float2 v = __bfloat1622float2(rowp[tid + 128 * j]);
            vj[j] = v;
            float zx = v.x + xr_r[j].x; zx = zx > 0.f ? zx : 0.2f * zx;
            float zy = v.y + xr_r[j].y; zy = zy > 0.f ? zy : 0.2f * zy;
            part = fmaf(zx, att_r[j].x, part);
            part = fmaf(zy, att_r[j].y, part);
        }
#pragma unroll
        for (int o = 16; o; o >>= 1) part += __shfl_xor_sync(0xffffffffu, part, o);
        if (lane == 0) red[warp] = part;
        __syncthreads();
        float e = red[0] + red[1] + red[2] + red[3];
        __syncthreads();
        float mn = fmaxf(m, e);
        float scale = __expf(m - mn);
        float p = __expf(e - mn);
        ssum = ssum * scale + p;
#pragma unroll
        for (int j = 0; j < 3; j++) {
            acc[j].x = fmaf(acc[j].x, scale, p * vj[j].x);
            acc[j].y = fmaf(acc[j].y, scale, p * vj[j].y);
        }
        m = mn;
    }
    float inv = 1.f / ssum;
#pragma unroll
    for (int j = 0; j < 3; j++) {
        int h = 2 * (tid + 128 * j);
        float2 gb = *(const float2*)(gbias + h);
        float2 ms = *(const float2*)(msg + (size_t)node * HH + h);
        float2 o;
        o.x = acc[j].x * inv + gb.x + ms.x;
        o.y = acc[j].y * inv + gb.y + ms.y;
        *(float2*)(g_msgg + (size_t)node * HH + h) = o;
    }
}

// ------------- diff node-0 path ---------------------------------------------
__global__ void collect0_kernel(const int* __restrict__ ei) {
    int b = blockIdx.x, tid = threadIdx.x;
    __shared__ int scnt;
    if (tid == 0) scnt = 0;
    __syncthreads();
    for (int e = tid; e < EE; e += 256) {
        int s = ei[b * 2 * EE + e], dd = ei[b * 2 * EE + EE + e];
        if ((unsigned)s < SS && dd == 0) {
            int p = atomicAdd(&scnt, 1);
            if (p < CAPD - 1) g_src0[b * CAPD + p] = s;
        }
    }
    __syncthreads();
    if (tid == 0) {
        int nd = min(scnt, CAPD - 1);
        g_src0[b * CAPD + nd] = 0;    // self loop
        g_nd[b] = nd + 1;
    }
}

// dxl[b,i,:] = diff[b,src_i,:] @ wl + bl     grid (3, CAPD, BB)
__global__ __launch_bounds__(256) void dxl_kernel(
    const float* __restrict__ diff, const float* __restrict__ wl,
    const float* __restrict__ bl)
{
    int b = blockIdx.z, i = blockIdx.y, ch = blockIdx.x, tid = threadIdx.x;
    if (i >= g_nd[b]) return;
    __shared__ float xrow[HH];
    int src = g_src0[b * CAPD + i];
    const float* xp = diff + (size_t)(b * SS + src) * HH;
    for (int k = tid; k < HH; k += 256) xrow[k] = xp[k];
    __syncthreads();
    int j = ch * 256 + tid;
    float a = bl[j];
#pragma unroll 4
    for (int k = 0; k < HH; k++) a = fmaf(xrow[k], wl[(size_t)k * HH + j], a);
    g_dxl[((size_t)b * CAPD + i) * HH + j] = a;
}

// xr0[b,:] = diff[b,0,:] @ wr + br      grid (3, BB)
__global__ __launch_bounds__(256) void xr0_kernel(
    const float* __restrict__ diff, const float* __restrict__ wr,
    const float* __restrict__ br)
{
    int b = blockIdx.y, ch = blockIdx.x, tid = threadIdx.x;
    __shared__ float xrow[HH];
    const float* xp = diff + (size_t)b * SS * HH;
    for (int k = tid; k < HH; k += 256) xrow[k] = xp[k];
    __syncthreads();
    int j = ch * 256 + tid;
    float a = br[j];
#pragma unroll 4
    for (int k = 0; k < HH; k++) a = fmaf(xrow[k], wr[(size_t)k * HH + j], a);
    g_xr0[b * HH + j] = a;
}

// softmax over the <=64 node-0 edges + weighted sum -> g_diffg0. grid (BB)
__global__ __launch_bounds__(256) void diff0_fin_kernel(
    const float* __restrict__ diff, const float* __restrict__ att,
    const float* __restrict__ gbias)
{
    int b = blockIdx.x, tid = threadIdx.x;
    int warp = tid >> 5, lane = tid & 31;
    __shared__ float xr0s[HH];
    __shared__ float evals[CAPD];
    for (int k = tid; k < HH; k += 256) xr0s[k] = g_xr0[b * HH + k];
    __syncthreads();
    int d = g_nd[b];
    // phase 1: logits (warp per edge)
    for (int i = warp; i < d; i += 8) {
        const float* row = g_dxl + ((size_t)b * CAPD + i) * HH;
        float s = 0.f;
        for (int k = lane; k < HH; k += 32) {
            float z = row[k] + xr0s[k];
            z = z > 0.f ? z : 0.2f * z;
            s = fmaf(z, att[k], s);
        }
#pragma unroll
        for (int o = 16; o; o >>= 1) s += __shfl_xor_sync(0xffffffffu, s, o);
        if (lane == 0) evals[i] = s;
    }
    __syncthreads();
    // phase 2: softmax over d (single warp)
    if (warp == 0) {
        float v0 = (lane < d) ? evals[lane] : -3.4e38f;
        float v1 = (lane + 32 < d) ? evals[lane + 32] : -3.4e38f;
        float m = fmaxf(v0, v1);
#pragma unroll
        for (int o = 16; o; o >>= 1) m = fmaxf(m, __shfl_xor_sync(0xffffffffu, m, o));
        float e0 = (lane < d) ? __expf(v0 - m) : 0.f;
        float e1 = (lane + 32 < d) ? __expf(v1 - m) : 0.f;
        float s = e0 + e1;
#pragma unroll
        for (int o = 16; o; o >>= 1) s += __shfl_xor_sync(0xffffffffu, s, o);
        float inv = 1.f / s;
        if (lane < d) evals[lane] = e0 * inv;
        if (lane + 32 < d) evals[lane + 32] = e1 * inv;
    }
    __syncthreads();
    // phase 3: weighted sum (3 outputs per thread)
#pragma unroll
    for (int c = 0; c < 3; c++) {
        int j = tid + 256 * c;
        float a = 0.f;
        for (int i = 0; i < d; i++)
            a = fmaf(evals[i], g_dxl[((size_t)b * CAPD + i) * HH + j], a);
        g_diffg0[b * HH + j] = a + gbias[j] + diff[(size_t)b * SS * HH + j];
    }
}

// q0 = diffg0 @ wq + bq     grid (3, BB)
__global__ __launch_bounds__(256) void q0_kernel(
    const float* __restrict__ wq, const float* __restrict__ bq)
{
    int b = blockIdx.y, ch = blockIdx.x, tid = threadIdx.x;
    __shared__ float xrow[HH];
    for (int k = tid; k < HH; k += 256) xrow[k] = g_diffg0[b * HH + k];
    __syncthreads();
    int j = ch * 256 + tid;
    float a = bq[j];
#pragma unroll 4
    for (int k = 0; k < HH; k++) a = fmaf(xrow[k], wq[(size_t)k * HH + j], a);
    g_q0[b * HH + j] = a;
}

// r[b,h,i] = (1/sqrt(96)) * sum_d wk[i][h*96+d] * q0[b][h*96+d]   grid (BB, NH)
__global__ __launch_bounds__(256) void r_kernel(const float* __restrict__ wk) {
    int b = blockIdx.x, h = blockIdx.y, tid = threadIdx.x;
    int warp = tid >> 5, lane = tid & 31;
    __shared__ float q0h[DHD];
    if (tid < DHD) q0h[tid] = g_q0[b * HH + h * DHD + tid];
    __syncthreads();
    const float RS = 0.10206207261596577f;
    for (int i = warp; i < HH; i += 8) {
        const float* wrow = wk + (size_t)i * HH + h * DHD;
        float s = wrow[lane] * q0h[lane]
                + wrow[lane + 32] * q0h[lane + 32]
                + wrow[lane + 64] * q0h[lane + 64];
#pragma unroll
        for (int o = 16; o; o >>= 1) s += __shfl_xor_sync(0xffffffffu, s, o);
        if (lane == 0) g_r[(b * NH + h) * HH + i] = s * RS;
    }
}

// scores: grid (BB, 8 chunks of 64 s). r staged in smem, msgg streamed once.
__global__ __launch_bounds__(256) void scores_kernel(const int* __restrict__ mask) {
    int b = blockIdx.x, ch = blockIdx.y, tid = threadIdx.x;
    int warp = tid >> 5, lane = tid & 31;
    __shared__ float rall[NH * HH];
    for (int t = tid; t < NH * HH; t += 256) rall[t] = g_r[(size_t)b * NH * HH + t];
    __syncthreads();
    for (int t = 0; t < 8; t++) {
        int s = ch * 64 + warp * 8 + t;
        const float4* row = (const float4*)(g_msgg + (size_t)(b * SS + s) * HH);
        float acc[NH];
#pragma unroll
        for (int h = 0; h < NH; h++) acc[h] = 0.f;
#pragma unroll
        for (int k = 0; k < 6; k++) {
            int idx = k * 32 + lane;
            float4 v = row[idx];
#pragma unroll
            for (int h = 0; h < NH; h++) {
                const float* rp = rall + h * HH + idx * 4;
                acc[h] = fmaf(v.x, rp[0], acc[h]);
                acc[h] = fmaf(v.y, rp[1], acc[h]);
                acc[h] = fmaf(v.z, rp[2], acc[h]);
                acc[h] = fmaf(v.w, rp[3], acc[h]);
            }
        }
#pragma unroll
        for (int o = 16; o; o >>= 1)
#pragma unroll
            for (int h = 0; h < NH; h++)
                acc[h] += __shfl_xor_sync(0xffffffffu, acc[h], o);
        if (lane == 0) {
            int mk = mask[b * SS + s];
#pragma unroll
            for (int h = 0; h < NH; h++)
                g_attn[(b * NH + h) * SS + s] = (mk == 0) ? NEGV : acc[h];
        }
    }
}

__global__ __launch_bounds__(256) void softmax_kernel() {
    int bh = blockIdx.x, tid = threadIdx.x;
    __shared__ float red[256];
    float* p = g_attn + (size_t)bh * SS;
    float v0 = p[tid], v1 = p[tid + 256];
    red[tid] = fmaxf(v0, v1); __syncthreads();
    for (int o = 128; o; o >>= 1) { if (tid < o) red[tid] = fmaxf(red[tid], red[tid + o]); __syncthreads(); }
    float m = red[0]; __syncthreads();
    float e0 = __expf(v0 - m), e1 = __expf(v1 - m);
    red[tid] = e0 + e1; __syncthreads();
    for (int o = 128; o; o >>= 1) { if (tid < o) red[tid] += red[tid + o]; __syncthreads(); }
    float inv = 1.f / red[0];
    p[tid] = e0 * inv; p[tid + 256] = e1 * inv;
}

// u[b,h,:] += sum over 64-s chunk of attn * msgg     grid (BB, 8)
__global__ __launch_bounds__(256) void u_kernel() {
    int b = blockIdx.x, ch = blockIdx.y, tid = threadIdx.x;
    __shared__ float aw[NH][64];
    for (int t = tid; t < NH * 64; t += 256) {
        int h = t >> 6, s = t & 63;
        aw[h][s] = g_attn[(b * NH + h) * SS + ch * 64 + s];
    }
    __syncthreads();
    int j0 = tid, j1 = tid + 256, j2 = tid + 512;
    float acc[NH][3];
#pragma unroll
    for (int h = 0; h < NH; h++) { acc[h][0] = acc[h][1] = acc[h][2] = 0.f; }
    for (int s = 0; s < 64; s++) {
        const float* mr = g_msgg + (size_t)(b * SS + ch * 64 + s) * HH;
        float x0 = mr[j0], x1 = mr[j1], x2 = mr[j2];
#pragma unroll
        for (int h = 0; h < NH; h++) {
            float w = aw[h][s];
            acc[h][0] = fmaf(w, x0, acc[h][0]);
            acc[h][1] = fmaf(w, x1, acc[h][1]);
            acc[h][2] = fmaf(w, x2, acc[h][2]);
        }
    }
#pragma unroll
    for (int h = 0; h < NH; h++) {
        atomicAdd(&g_u[(b * NH + h) * HH + j0], acc[h][0]);
        atomicAdd(&g_u[(b * NH + h) * HH + j1], acc[h][1]);
        atomicAdd(&g_u[(b * NH + h) * HH + j2], acc[h][2]);
    }
}

// ctx[b,j] = u[b, j/96, :] . wv[:,j] + bv[j]   grid (3, BB)
__global__ __launch_bounds__(256) void ctx_kernel(
    const float* __restrict__ wv, const float* __restrict__ bv)
{
    int b = blockIdx.y, ch = blockIdx.x, tid = threadIdx.x;
    __shared__ float us[NH * HH];
    for (int t = tid; t < NH * HH; t += 256) us[t] = g_u[(size_t)b * NH * HH + t];
    __syncthreads();
    int j = ch * 256 + tid;
    const float* up = us + (j / DHD) * HH;
    float a = bv[j];
#pragma unroll 4
    for (int k = 0; k < HH; k++) a = fmaf(up[k], wv[(size_t)k * HH + j], a);
    g_ctx[b * HH + j] = a;
}

// f[b,j] = ctx @ wo + bo + diffg0      grid (3, BB)
__global__ __launch_bounds__(256) void fwo_kernel(
    const float* __restrict__ wo, const float* __restrict__ bo)
{
    int b = blockIdx.y, ch = blockIdx.x, tid = threadIdx.x;
    __shared__ float crow[HH];
    for (int k = tid; k < HH; k += 256) crow[k] = g_ctx[b * HH + k];
    __syncthreads();
    int j = ch * 256 + tid;
    float a = bo[j];
#pragma unroll 4
    for (int k = 0; k < HH; k++) a = fmaf(crow[k], wo[(size_t)k * HH + j], a);
    g_f[b * HH + j] = a + g_diffg0[b * HH + j];
}

// LayerNorm     grid (BB)
__global__ __launch_bounds__(256) void ln_kernel(
    const float* __restrict__ lng, const float* __restrict__ lnb)
{
    int b = blockIdx.x, tid = threadIdx.x;
    __shared__ float red[256];
    float f0 = g_f[b * HH + tid], f1 = g_f[b * HH + tid + 256], f2 = g_f[b * HH + tid + 512];
    red[tid] = f0 + f1 + f2; __syncthreads();
    for (int o = 128; o; o >>= 1) { if (tid < o) red[tid] += red[tid + o]; __syncthreads(); }
    float mu = red[0] * (1.f / HH); __syncthreads();
    float d0 = f0 - mu, d1 = f1 - mu, d2 = f2 - mu;
    red[tid] = d0 * d0 + d1 * d1 + d2 * d2; __syncthreads();
    for (int o = 128; o; o >>= 1) { if (tid < o) red[tid] += red[tid + o]; __syncthreads(); }
    float rs = rsqrtf(red[0] * (1.f / HH) + 1e-5f);
    g_fln[b * HH + tid]       = d0 * rs * lng[tid]       + lnb[tid];
    g_fln[b * HH + tid + 256] = d1 * rs * lng[tid + 256] + lnb[tid + 256];
    g_fln[b * HH + tid + 512] = d2 * rs * lng[tid + 512] + lnb[tid + 512];
}

// fc0 relu    grid (2, BB)
__global__ __launch_bounds__(256) void fc0_kernel(
    const float* __restrict__ f0w, const float* __restrict__ f0b)
{
    int b = blockIdx.y, ch = blockIdx.x, tid = threadIdx.x;
    __shared__ float xrow[HH];
    for (int k = tid; k < HH; k += 256) xrow[k] = g_fln[b * HH + k];
    __syncthreads();
    int o = ch * 256 + tid;
    float a = f0b[o];
#pragma unroll 4
    for (int k = 0; k < HH; k++) a = fmaf(xrow[k], f0w[(size_t)k * 512 + o], a);
    g_h1[b * 512 + o] = a > 0.f ? a : 0.f;
}

// fc1 relu + fc2     grid (BB)
__global__ __launch_bounds__(256) void fc12_kernel(
    const float* __restrict__ f1w, const float* __restrict__ f1b,
    const float* __restrict__ f2w, const float* __restrict__ f2b,
    float* __restrict__ out)
{
    int b = blockIdx.x, tid = threadIdx.x;
    __shared__ float h1[512], h2[128];
    for (int k = tid; k < 512; k += 256) h1[k] = g_h1[b * 512 + k];
    __syncthreads();
    if (tid < 128) {
        float a = f1b[tid];
#pragma unroll 4
        for (int k = 0; k < 512; k++) a = fmaf(h1[k], f1w[k * 128 + tid], a);
        h2[tid] = a > 0.f ? a : 0.f;
    }
    __syncthreads();
    if (tid < 2) {
        float a = f2b[tid];
        for (int k = 0; k < 128; k++) a = fmaf(h2[k], f2w[k * 2 + tid], a);
        out[b * 2 + tid] = a;
    }
}

extern "C" void kernel_launch(void* const* d_in, const int* in_sizes, int n_in,
                              void* d_out, int out_size) {
    const float* diff  = (const float*)d_in[0];
    const float* msg   = (const float*)d_in[1];
    const int*   mask  = (const int*)d_in[2];
    const int*   ei_d  = (const int*)d_in[3];
    const int*   ei_m  = (const int*)d_in[4];
    const float* wl    = (const float*)d_in[5];
    const float* bl    = (const float*)d_in[6];
    const float* wr    = (const float*)d_in[7];
    const float* br    = (const float*)d_in[8];
    const float* att   = (const float*)d_in[9];
    const float* gbias = (const float*)d_in[10];
    const float* wq    = (const float*)d_in[11];
    const float* bq    = (const float*)d_in[12];
    const float* wk    = (const float*)d_in[13];
    const float* wv    = (const float*)d_in[15];
    const float* bv    = (const float*)d_in[16];
    const float* wo    = (const float*)d_in[17];
    const float* bo    = (const float*)d_in[18];
    const float* lng   = (const float*)d_in[19];
    const float* lnb   = (const float*)d_in[20];
    const float* f0w   = (const float*)d_in[21];
    const float* f0b   = (const float*)d_in[22];
    const float* f1w   = (const float*)d_in[23];
    const float* f1b   = (const float*)d_in[24];
    const float* f2w   = (const float*)d_in[25];
    const float* f2b   = (const float*)d_in[26];
    float* out = (float*)d_out;

    zero_kernel<<<768, 256>>>();                                        // 0
    convert_a_kernel<<<BB * SS * HH / 1024, 256>>>(msg);                // 1
    convert_w_kernel<<<dim3(HH / 32, HH / 32, 2), 256>>>(wl, wr);       // 2
    gemm_bf16_kernel<<<dim3(12, (BB * SS) / BM), 256>>>(bl, br);        // 3  <- ncu
    count_kernel<<<512, 256>>>(ei_m);                                   // 4
    scan_kernel<<<BB, 512>>>();                                         // 5
    scatter_kernel<<<512, 256>>>(ei_m);                                 // 6
    collect0_kernel<<<BB, 256>>>(ei_d);                                 // 7
    dxl_kernel<<<dim3(3, CAPD, BB), 256>>>(diff, wl, bl);               // 8
    xr0_kernel<<<dim3(3, BB), 256>>>(diff, wr, br);                     // 9
    gat_node_kernel<<<dim3(SS, BB), 128>>>(att, gbias, msg);            // 10
    diff0_fin_kernel<<<BB, 256>>>(diff, att, gbias);                    // 11
    q0_kernel<<<dim3(3, BB), 256>>>(wq, bq);                            // 12
    r_kernel<<<dim3(BB, NH), 256>>>(wk);                                // 13
    scores_kernel<<<dim3(BB, 8), 256>>>(mask);                          // 14
    softmax_kernel<<<BB * NH, 256>>>();                                 // 15
    u_kernel<<<dim3(BB, 8), 256>>>();                                   // 16
    ctx_kernel<<<dim3(3, BB), 256>>>(wv, bv);                           // 17
    fwo_kernel<<<dim3(3, BB), 256>>>(wo, bo);                           // 18
    ln_kernel<<<BB, 256>>>(lng, lnb);                                   // 19
    fc0_kernel<<<dim3(2, BB), 256>>>(f0w, f0b);                         // 20
    fc12_kernel<<<BB, 256>>>(f1w, f1b, f2w, f2b, out);                  // 21
}

// round 7
// speedup vs baseline: 2.5989x; 1.2505x over previous
#include <cuda_runtime.h>
#include <cuda_bf16.h>
#include <math.h>

#define BB 32
#define SS 512
#define HH 768
#define EE 4096
#define NH 8
#define DHD 96
#define NEGV -1000000000.0f
#define CAPD 64

#define BM 128
#define BN 128
#define BKK 32

// ------------- scratch ------------------------------------------------------
__device__ __nv_bfloat16 g_xlbf[BB * SS * HH];
__device__ __nv_bfloat16 g_xrbf[BB * SS * HH];
__device__ float g_msgg[BB * SS * HH];
__device__ int   g_cnt[BB * SS];
__device__ int   g_off[BB * SS];
__device__ int   g_esrc[BB * EE];
__device__ int   g_src0[BB * CAPD];
__device__ int   g_nd[BB];
__device__ float g_dxl[BB * CAPD * HH];
__device__ float g_xr0[BB * HH];
__device__ float g_diffg0[BB * HH];
__device__ float g_r[BB * NH * HH];
__device__ float g_attn[BB * NH * SS];
__device__ float g_u[BB * NH * HH];
__device__ float g_ctx[BB * HH];
__device__ float g_f[BB * HH];
__device__ float g_h1[BB * 512];
__device__ __nv_bfloat16 g_a_bf[BB * SS * HH];
__device__ __nv_bfloat16 g_w_bf[2 * HH * HH];

// ------------- fused CSR build (per batch) -----------------------------------
__global__ __launch_bounds__(512) void csr_kernel(const int* __restrict__ ei) {
    int b = blockIdx.x, tid = threadIdx.x;
    __shared__ int cnt[SS], sc[SS], cur[SS];
    cnt[tid] = 0;
    __syncthreads();
    for (int e = tid; e < EE; e += 512) {
        int s = ei[b * 2 * EE + e], d = ei[b * 2 * EE + EE + e];
        if ((unsigned)s < SS && (unsigned)d < SS) atomicAdd(&cnt[d], 1);
    }
    __syncthreads();
    int c = cnt[tid];
    sc[tid] = c;
    __syncthreads();
    for (int off = 1; off < SS; off <<= 1) {
        int t = (tid >= off) ? sc[tid - off] : 0;
        __syncthreads();
        sc[tid] += t;
        __syncthreads();
    }
    int ex = sc[tid] - c;
    g_cnt[b * SS + tid] = c;
    g_off[b * SS + tid] = ex;
    cur[tid] = ex;
    __syncthreads();
    for (int e = tid; e < EE; e += 512) {
        int s = ei[b * 2 * EE + e], d = ei[b * 2 * EE + EE + e];
        if ((unsigned)s < SS && (unsigned)d < SS) {
            int p = atomicAdd(&cur[d], 1);
            g_esrc[b * EE + p] = s;
        }
    }
}

// ------------- fp32 -> bf16 converts ----------------------------------------
__global__ void convert_a_kernel(const float* __restrict__ A) {
    int idx = blockIdx.x * 256 + threadIdx.x;
    float4 v = *(const float4*)(A + (size_t)idx * 4);
    *(__nv_bfloat162*)(g_a_bf + (size_t)idx * 4)     = __floats2bfloat162_rn(v.x, v.y);
    *(__nv_bfloat162*)(g_a_bf + (size_t)idx * 4 + 2) = __floats2bfloat162_rn(v.z, v.w);
}

__global__ void convert_w_kernel(const float* __restrict__ Wl, const float* __restrict__ Wr) {
    __shared__ float sm[32][33];
    const float* W = blockIdx.z ? Wr : Wl;
    __nv_bfloat16* Wt = g_w_bf + (size_t)blockIdx.z * HH * HH;
    int n0 = blockIdx.x * 32, k0 = blockIdx.y * 32;
    int c = threadIdx.x & 31, r0 = threadIdx.x >> 5;
    for (int r = r0; r < 32; r += 8)
        sm[r][c] = W[(size_t)(k0 + r) * HH + n0 + c];
    __syncthreads();
    for (int r = r0; r < 32; r += 8)
        Wt[(size_t)(n0 + r) * HH + k0 + c] = __float2bfloat16(sm[c][r]);
}

// ------------- helpers ------------------------------------------------------
__device__ __forceinline__ void mma_bf16(float c[4], const unsigned a[4], const unsigned b[2]) {
    asm volatile(
        "mma.sync.aligned.m16n8k16.row.col.f32.bf16.bf16.f32 "
        "{%0,%1,%2,%3}, {%4,%5,%6,%7}, {%8,%9}, {%0,%1,%2,%3};"
        : "+f"(c[0]), "+f"(c[1]), "+f"(c[2]), "+f"(c[3])
        : "r"(a[0]), "r"(a[1]), "r"(a[2]), "r"(a[3]), "r"(b[0]), "r"(b[1]));
}

// ------------- bf16 GEMM -> bf16 outputs g_xlbf/g_xrbf -----------------------
__global__ __launch_bounds__(256) void gemm_bf16_kernel(
    const float* __restrict__ bl, const float* __restrict__ br)
{
    const int K = HH, N = HH;
    int bx = blockIdx.x;
    int which = (bx >= 6);
    const __nv_bfloat16* Wt = g_w_bf + (size_t)which * HH * HH;
    const float* bias = which ? br : bl;
    __nv_bfloat16* C = which ? g_xrbf : g_xlbf;
    int bn = (which ? bx - 6 : bx) * BN;
    int bm = blockIdx.y * BM;

    __shared__ __nv_bfloat16 As[BM][40];
    __shared__ __nv_bfloat16 Bs[BN][40];
    int tid = threadIdx.x;
    int wid = tid >> 5, lane = tid & 31;
    int wm = wid >> 2, wn = wid & 3;
    int g = lane >> 2, c2 = (lane & 3) << 1;

    float acc[4][4][4];
#pragma unroll
    for (int i = 0; i < 4; i++)
#pragma unroll
        for (int j = 0; j < 4; j++)
#pragma unroll
            for (int t = 0; t < 4; t++) acc[i][j][t] = 0.f;

    int lrow = tid >> 2;
    int lkq  = (tid & 3) << 3;

    uint4 av0, av1, bv0, bv1;
    av0 = *(const uint4*)(g_a_bf + (size_t)(bm + lrow) * K + lkq);
    av1 = *(const uint4*)(g_a_bf + (size_t)(bm + 64 + lrow) * K + lkq);
    bv0 = *(const uint4*)(Wt + (size_t)(bn + lrow) * K + lkq);
    bv1 = *(const uint4*)(Wt + (size_t)(bn + 64 + lrow) * K + lkq);

    for (int kt = 0; kt < K; kt += BKK) {
        *(uint4*)&As[lrow][lkq]      = av0;
        *(uint4*)&As[lrow + 64][lkq] = av1;
        *(uint4*)&Bs[lrow][lkq]      = bv0;
        *(uint4*)&Bs[lrow + 64][lkq] = bv1;
        __syncthreads();
        if (kt + BKK < K) {
            av0 = *(const uint4*)(g_a_bf + (size_t)(bm + lrow) * K + kt + BKK + lkq);
            av1 = *(const uint4*)(g_a_bf + (size_t)(bm + 64 + lrow) * K + kt + BKK + lkq);
            bv0 = *(const uint4*)(Wt + (size_t)(bn + lrow) * K + kt + BKK + lkq);
            bv1 = *(const uint4*)(Wt + (size_t)(bn + 64 + lrow) * K + kt + BKK + lkq);
        }
#pragma unroll
        for (int ks = 0; ks < 2; ks++) {
            int k0 = ks << 4;
            unsigned af[4][4], bf[4][2];
#pragma unroll
            for (int i = 0; i < 4; i++) {
                int r = wm * 64 + i * 16;
                af[i][0] = *(const unsigned*)&As[r + g][k0 + c2];
                af[i][1] = *(const unsigned*)&As[r + 8 + g][k0 + c2];
                af[i][2] = *(const unsigned*)&As[r + g][k0 + 8 + c2];
                af[i][3] = *(const unsigned*)&As[r + 8 + g][k0 + 8 + c2];
            }
#pragma unroll
            for (int j = 0; j < 4; j++) {
                int n0 = wn * 32 + j * 8;
                bf[j][0] = *(const unsigned*)&Bs[n0 + g][k0 + c2];
                bf[j][1] = *(const unsigned*)&Bs[n0 + g][k0 + 8 + c2];
            }
#pragma unroll
            for (int i = 0; i < 4; i++)
#pragma unroll
                for (int j = 0; j < 4; j++)
                    mma_bf16(acc[i][j], af[i], bf[j]);
        }
        __syncthreads();
    }

#pragma unroll
    for (int i = 0; i < 4; i++) {
#pragma unroll
        for (int j = 0; j < 4; j++) {
            int row = bm + wm * 64 + i * 16 + g;
            int col = bn + wn * 32 + j * 8 + c2;
            float b0 = bias[col], b1 = bias[col + 1];
            *(__nv_bfloat162*)(C + (size_t)row * N + col) =
                __floats2bfloat162_rn(acc[i][j][0] + b0, acc[i][j][1] + b1);
            *(__nv_bfloat162*)(C + (size_t)(row + 8) * N + col) =
                __floats2bfloat162_rn(acc[i][j][2] + b0, acc[i][j][3] + b1);
        }
    }
}

// ------------- msg GAT: pipelined one-pass online softmax --------------------
__global__ __launch_bounds__(128) void gat_node_kernel(
    const float* __restrict__ att, const float* __restrict__ gbias,
    const float* __restrict__ msg)
{
    int n = blockIdx.x, b = blockIdx.y, tid = threadIdx.x;
    int node = b * SS + n;
    __shared__ float red[2][4];
    int warp = tid >> 5, lane = tid & 31;

    const __nv_bfloat162* xrp = (const __nv_bfloat162*)(g_xrbf + (size_t)node * HH);
    float2 xr_r[3], att_r[3], acc[3];
#pragma unroll
    for (int j = 0; j < 3; j++) {
        int p = tid + 128 * j;
        xr_r[j]  = __bfloat1622float2(xrp[p]);
        att_r[j] = *(const float2*)(att + 2 * p);
        acc[j] = make_float2(0.f, 0.f);
    }
    int deg = g_cnt[node];
    int base = b * EE + g_off[node];
    float m = -3.4e38f, ssum = 0.f;

    int src0 = (deg > 0) ? g_esrc[base] : n;
    float2 vj[3];
    {
        const __nv_bfloat162* rp = (const __nv_bfloat162*)(g_xlbf + (size_t)(b * SS + src0) * HH);
#pragma unroll
        for (int j = 0; j < 3; j++) vj[j] = __bfloat1622float2(rp[tid + 128 * j]);
    }

    for (int i = 0; i <= deg; i++) {
        // start next row load (hidden under reduce)
        float2 nv[3];
        if (i < deg) {
            int nsrc = (i + 1 < deg) ? g_esrc[base + i + 1] : n;
            const __nv_bfloat162* rp = (const __nv_bfloat162*)(g_xlbf + (size_t)(b * SS + nsrc) * HH);
#pragma unroll
            for (int j = 0; j < 3; j++) nv[j] = __bfloat1622float2(rp[tid + 128 * j]);
        }
        float part = 0.f;
#pragma unroll
        for (int j = 0; j < 3; j++) {
            float zx = vj[j].x + xr_r[j].x; zx = zx > 0.f ? zx : 0.2f * zx;
            float zy = vj[j].y + xr_r[j].y; zy = zy > 0.f ? zy : 0.2f * zy;
            part = fmaf(zx, att_r[j].x, part);
            part = fmaf(zy, att_r[j].y, part);
        }
#pragma unroll
        for (int o = 16; o; o >>= 1) part += __shfl_xor_sync(0xffffffffu, part, o);
        int pb = i & 1;
        if (lane == 0) red[pb][warp] = part;
        __syncthreads();
        float e = red[pb][0] + red[pb][1] + red[pb][2] + red[pb][3];
        float mn = fmaxf(m, e);
        float scale = __expf(m - mn);
        float p = __expf(e - mn);
        ssum = ssum * scale + p;
#pragma unroll
        for (int j = 0; j < 3; j++) {
            acc[j].x = fmaf(acc[j].x, scale, p * vj[j].x);
            acc[j].y = fmaf(acc[j].y, scale, p * vj[j].y);
            vj[j] = nv[j];
        }
        m = mn;
    }
    float inv = 1.f / ssum;
#pragma unroll
    for (int j = 0; j < 3; j++) {
        int h = 2 * (tid + 128 * j);
        float2 gb = *(const float2*)(gbias + h);
        float2 ms = *(const float2*)(msg + (size_t)node * HH + h);
        float2 o;
        o.x = acc[j].x * inv + gb.x + ms.x;
        o.y = acc[j].y * inv + gb.y + ms.y;
        *(float2*)(g_msgg + (size_t)node * HH + h) = o;
    }
}

// ------------- diff node-0 path ---------------------------------------------
__global__ void collect0_kernel(const int* __restrict__ ei) {
    int b = blockIdx.x, tid = threadIdx.x;
    __shared__ int scnt;
    if (tid == 0) scnt = 0;
    __syncthreads();
    for (int e = tid; e < EE; e += 256) {
        int s = ei[b * 2 * EE + e], dd = ei[b * 2 * EE + EE + e];
        if ((unsigned)s < SS && dd == 0) {
            int p = atomicAdd(&scnt, 1);
            if (p < CAPD - 1) g_src0[b * CAPD + p] = s;
        }
    }
    __syncthreads();
    if (tid == 0) {
        int nd = min(scnt, CAPD - 1);
        g_src0[b * CAPD + nd] = 0;
        g_nd[b] = nd + 1;
    }
}

// dxl[b,i,:] = diff[b,src_i,:] @ wl + bl     grid (3, CAPD, BB)
__global__ __launch_bounds__(256) void dxl_kernel(
    const float* __restrict__ diff, const float* __restrict__ wl,
    const float* __restrict__ bl)
{
    int b = blockIdx.z, i = blockIdx.y, ch = blockIdx.x, tid = threadIdx.x;
    if (i >= g_nd[b]) return;
    __shared__ float xrow[HH];
    int src = g_src0[b * CAPD + i];
    const float* xp = diff + (size_t)(b * SS + src) * HH;
    for (int k = tid; k < HH; k += 256) xrow[k] = xp[k];
    __syncthreads();
    int j = ch * 256 + tid;
    float a0 = bl[j], a1 = 0.f, a2 = 0.f, a3 = 0.f;
#pragma unroll 4
    for (int k = 0; k < HH; k += 4) {
        a0 = fmaf(xrow[k],     wl[(size_t)k * HH + j], a0);
        a1 = fmaf(xrow[k + 1], wl[(size_t)(k + 1) * HH + j], a1);
        a2 = fmaf(xrow[k + 2], wl[(size_t)(k + 2) * HH + j], a2);
        a3 = fmaf(xrow[k + 3], wl[(size_t)(k + 3) * HH + j], a3);
    }
    g_dxl[((size_t)b * CAPD + i) * HH + j] = (a0 + a1) + (a2 + a3);
}

// xr0[b,:] = diff[b,0,:] @ wr + br      grid (3, BB)
__global__ __launch_bounds__(256) void xr0_kernel(
    const float* __restrict__ diff, const float* __restrict__ wr,
    const float* __restrict__ br)
{
    int b = blockIdx.y, ch = blockIdx.x, tid = threadIdx.x;
    __shared__ float xrow[HH];
    const float* xp = diff + (size_t)b * SS * HH;
    for (int k = tid; k < HH; k += 256) xrow[k] = xp[k];
    __syncthreads();
    int j = ch * 256 + tid;
    float a0 = br[j], a1 = 0.f, a2 = 0.f, a3 = 0.f;
#pragma unroll 4
    for (int k = 0; k < HH; k += 4) {
        a0 = fmaf(xrow[k],     wr[(size_t)k * HH + j], a0);
        a1 = fmaf(xrow[k + 1], wr[(size_t)(k + 1) * HH + j], a1);
        a2 = fmaf(xrow[k + 2], wr[(size_t)(k + 2) * HH + j], a2);
        a3 = fmaf(xrow[k + 3], wr[(size_t)(k + 3) * HH + j], a3);
    }
    g_xr0[b * HH + j] = (a0 + a1) + (a2 + a3);
}

// softmax over node-0 edges + weighted sum -> g_diffg0. grid (BB)
__global__ __launch_bounds__(256) void diff0_fin_kernel(
    const float* __restrict__ diff, const float* __restrict__ att,
    const float* __restrict__ gbias)
{
    int b = blockIdx.x, tid = threadIdx.x;
    int warp = tid >> 5, lane = tid & 31;
    __shared__ float xr0s[HH];
    __shared__ float evals[CAPD];
    for (int k = tid; k < HH; k += 256) xr0s[k] = g_xr0[b * HH + k];
    __syncthreads();
    int d = g_nd[b];
    for (int i = warp; i < d; i += 8) {
        const float* row = g_dxl + ((size_t)b * CAPD + i) * HH;
        float s = 0.f;
        for (int k = lane; k < HH; k += 32) {
            float z = row[k] + xr0s[k];
            z = z > 0.f ? z : 0.2f * z;
            s = fmaf(z, att[k], s);
        }
#pragma unroll
        for (int o = 16; o; o >>= 1) s += __shfl_xor_sync(0xffffffffu, s, o);
        if (lane == 0) evals[i] = s;
    }
    __syncthreads();
    if (warp == 0) {
        float v0 = (lane < d) ? evals[lane] : -3.4e38f;
        float v1 = (lane + 32 < d) ? evals[lane + 32] : -3.4e38f;
        float m = fmaxf(v0, v1);
#pragma unroll
        for (int o = 16; o; o >>= 1) m = fmaxf(m, __shfl_xor_sync(0xffffffffu, m, o));
        float e0 = (lane < d) ? __expf(v0 - m) : 0.f;
        float e1 = (lane + 32 < d) ? __expf(v1 - m) : 0.f;
        float s = e0 + e1;
#pragma unroll
        for (int o = 16; o; o >>= 1) s += __shfl_xor_sync(0xffffffffu, s, o);
        float inv = 1.f / s;
        if (lane < d) evals[lane] = e0 * inv;
        if (lane + 32 < d) evals[lane + 32] = e1 * inv;
    }
    __syncthreads();
#pragma unroll
    for (int c = 0; c < 3; c++) {
        int j = tid + 256 * c;
        float a = 0.f;
        for (int i = 0; i < d; i++)
            a = fmaf(evals[i], g_dxl[((size_t)b * CAPD + i) * HH + j], a);
        g_diffg0[b * HH + j] = a + gbias[j] + diff[(size_t)b * SS * HH + j];
    }
}

// q0 (head slice) + r fold     grid (BB, NH)
__global__ __launch_bounds__(256) void rq0_kernel(
    const float* __restrict__ wq, const float* __restrict__ bq,
    const float* __restrict__ wk)
{
    int b = blockIdx.x, h = blockIdx.y, tid = threadIdx.x;
    int warp = tid >> 5, lane = tid & 31;
    __shared__ float dg[HH];
    __shared__ float q0h[DHD];
    for (int k = tid; k < HH; k += 256) dg[k] = g_diffg0[b * HH + k];
    __syncthreads();
    if (tid < DHD) {
        int col = h * DHD + tid;
        float a0 = bq[col], a1 = 0.f, a2 = 0.f, a3 = 0.f;
#pragma unroll 4
        for (int k = 0; k < HH; k += 4) {
            a0 = fmaf(dg[k],     wq[(size_t)k * HH + col], a0);
            a1 = fmaf(dg[k + 1], wq[(size_t)(k + 1) * HH + col], a1);
            a2 = fmaf(dg[k + 2], wq[(size_t)(k + 2) * HH + col], a2);
            a3 = fmaf(dg[k + 3], wq[(size_t)(k + 3) * HH + col], a3);
        }
        q0h[tid] = (a0 + a1) + (a2 + a3);
    }
    __syncthreads();
    const float RS = 0.10206207261596577f;
    for (int i = warp; i < HH; i += 8) {
        const float* wrow = wk + (size_t)i * HH + h * DHD;
        float s = wrow[lane] * q0h[lane]
                + wrow[lane + 32] * q0h[lane + 32]
                + wrow[lane + 64] * q0h[lane + 64];
#pragma unroll
        for (int o = 16; o; o >>= 1) s += __shfl_xor_sync(0xffffffffu, s, o);
        if (lane == 0) g_r[(b * NH + h) * HH + i] = s * RS;
    }
}

// scores: grid (BB, 8 chunks of 64 s)
__global__ __launch_bounds__(256) void scores_kernel(const int* __restrict__ mask) {
    int b = blockIdx.x, ch = blockIdx.y, tid = threadIdx.x;
    int warp = tid >> 5, lane = tid & 31;
    __shared__ float rall[NH * HH];
    for (int t = tid; t < NH * HH; t += 256) rall[t] = g_r[(size_t)b * NH * HH + t];
    __syncthreads();
    for (int t = 0; t < 8; t++) {
        int s = ch * 64 + warp * 8 + t;
        const float4* row = (const float4*)(g_msgg + (size_t)(b * SS + s) * HH);
        float acc[NH];
#pragma unroll
        for (int h = 0; h < NH; h++) acc[h] = 0.f;
#pragma unroll
        for (int k = 0; k < 6; k++) {
            int idx = k * 32 + lane;
            float4 v = row[idx];
#pragma unroll
            for (int h = 0; h < NH; h++) {
                const float* rp = rall + h * HH + idx * 4;
                acc[h] = fmaf(v.x, rp[0], acc[h]);
                acc[h] = fmaf(v.y, rp[1], acc[h]);
                acc[h] = fmaf(v.z, rp[2], acc[h]);
                acc[h] = fmaf(v.w, rp[3], acc[h]);
            }
        }
#pragma unroll
        for (int o = 16; o; o >>= 1)
#pragma unroll
            for (int h = 0; h < NH; h++)
                acc[h] += __shfl_xor_sync(0xffffffffu, acc[h], o);
        if (lane == 0) {
            int mk = mask[b * SS + s];
#pragma unroll
            for (int h = 0; h < NH; h++)
                g_attn[(b * NH + h) * SS + s] = (mk == 0) ? NEGV : acc[h];
        }
    }
}

__global__ __launch_bounds__(256) void softmax_kernel() {
    int bh = blockIdx.x, tid = threadIdx.x;
    __shared__ float red[256];
    float* p = g_attn + (size_t)bh * SS;
    float v0 = p[tid], v1 = p[tid + 256];
    red[tid] = fmaxf(v0, v1); __syncthreads();
    for (int o = 128; o; o >>= 1) { if (tid < o) red[tid] = fmaxf(red[tid], red[tid + o]); __syncthreads(); }
    float m = red[0]; __syncthreads();
    float e0 = __expf(v0 - m), e1 = __expf(v1 - m);
    red[tid] = e0 + e1; __syncthreads();
    for (int o = 128; o; o >>= 1) { if (tid < o) red[tid] += red[tid + o]; __syncthreads(); }
    float inv = 1.f / red[0];
    p[tid] = e0 * inv; p[tid + 256] = e1 * inv;
}

// u: deterministic, no atomics.  grid (BB, 3 col-chunks)
__global__ __launch_bounds__(256) void u_kernel() {
    int b = blockIdx.x, ch = blockIdx.y, tid = threadIdx.x;
    __shared__ float aw[NH][SS];
    for (int t = tid; t < NH * SS; t += 256)
        aw[t >> 9][t & 511] = g_attn[(size_t)b * NH * SS + t];
    __syncthreads();
    int j = ch * 256 + tid;
    float acc[NH];
#pragma unroll
    for (int h = 0; h < NH; h++) acc[h] = 0.f;
#pragma unroll 4
    for (int s = 0; s < SS; s++) {
        float v = g_msgg[(size_t)(b * SS + s) * HH + j];
#pragma unroll
        for (int h = 0; h < NH; h++) acc[h] = fmaf(aw[h][s], v, acc[h]);
    }
#pragma unroll
    for (int h = 0; h < NH; h++)
        g_u[(size_t)(b * NH + h) * HH + j] = acc[h];
}

// ctx[b,j] = u[b, j/96, :] . wv[:,j] + bv[j]   grid (3, BB)
__global__ __launch_bounds__(256) void ctx_kernel(
    const float* __restrict__ wv, const float* __restrict__ bv)
{
    int b = blockIdx.y, ch = blockIdx.x, tid = threadIdx.x;
    __shared__ float us[NH * HH];
    for (int t = tid; t < NH * HH; t += 256) us[t] = g_u[(size_t)b * NH * HH + t];
    __syncthreads();
    int j = ch * 256 + tid;
    const float* up = us + (j / DHD) * HH;
    float a0 = bv[j], a1 = 0.f, a2 = 0.f, a3 = 0.f;
#pragma unroll 4
    for (int k = 0; k < HH; k += 4) {
        a0 = fmaf(up[k],     wv[(size_t)k * HH + j], a0);
        a1 = fmaf(up[k + 1], wv[(size_t)(k + 1) * HH + j], a1);
        a2 = fmaf(up[k + 2], wv[(size_t)(k + 2) * HH + j], a2);
        a3 = fmaf(up[k + 3], wv[(size_t)(k + 3) * HH + j], a3);
    }
    g_ctx[b * HH + j] = (a0 + a1) + (a2 + a3);
}

// f[b,j] = ctx @ wo + bo + diffg0      grid (3, BB)
__global__ __launch_bounds__(256) void fwo_kernel(
    const float* __restrict__ wo, const float* __restrict__ bo)
{
    int b = blockIdx.y, ch = blockIdx.x, tid = threadIdx.x;
    __shared__ float crow[HH];
    for (int k = tid; k < HH; k += 256) crow[k] = g_ctx[b * HH + k];
    __syncthreads();
    int j = ch * 256 + tid;
    float a0 = bo[j], a1 = 0.f, a2 = 0.f, a3 = 0.f;
#pragma unroll 4
    for (int k = 0; k < HH; k += 4) {
        a0 = fmaf(crow[k],     wo[(size_t)k * HH + j], a0);
        a1 = fmaf(crow[k + 1], wo[(size_t)(k + 1) * HH + j], a1);
        a2 = fmaf(crow[k + 2], wo[(size_t)(k + 2) * HH + j], a2);
        a3 = fmaf(crow[k + 3], wo[(size_t)(k + 3) * HH + j], a3);
    }
    g_f[b * HH + j] = (a0 + a1) + (a2 + a3) + g_diffg0[b * HH + j];
}

// LN + fc0 relu    grid (2, BB)
__global__ __launch_bounds__(256) void fc0ln_kernel(
    const float* __restrict__ lng, const float* __restrict__ lnb,
    const float* __restrict__ f0w, const float* __restrict__ f0b)
{
    int b = blockIdx.y, ch = blockIdx.x, tid = threadIdx.x;
    __shared__ float x[HH];
    __shared__ float red[256];
    float f0 = g_f[b * HH + tid], f1 = g_f[b * HH + tid + 256], f2 = g_f[b * HH + tid + 512];
    red[tid] = f0 + f1 + f2; __syncthreads();
    for (int o = 128; o; o >>= 1) { if (tid < o) red[tid] += red[tid + o]; __syncthreads(); }
    float mu = red[0] * (1.f / HH); __syncthreads();
    float d0 = f0 - mu, d1 = f1 - mu, d2 = f2 - mu;
    red[tid] = d0 * d0 + d1 * d1 + d2 * d2; __syncthreads();
    for (int o = 128; o; o >>= 1) { if (tid < o) red[tid] += red[tid + o]; __syncthreads(); }
    float rs = rsqrtf(red[0] * (1.f / HH) + 1e-5f);
    x[tid]       = d0 * rs * lng[tid]       + lnb[tid];
    x[tid + 256] = d1 * rs * lng[tid + 256] + lnb[tid + 256];
    x[tid + 512] = d2 * rs * lng[tid + 512] + lnb[tid + 512];
    __syncthreads();
    int o = ch * 256 + tid;
    float a0 = f0b[o], a1 = 0.f, a2 = 0.f, a3 = 0.f;
#pragma unroll 4
    for (int k = 0; k < HH; k += 4) {
        a0 = fmaf(x[k],     f0w[(size_t)k * 512 + o], a0);
        a1 = fmaf(x[k + 1], f0w[(size_t)(k + 1) * 512 + o], a1);
        a2 = fmaf(x[k + 2], f0w[(size_t)(k + 2) * 512 + o], a2);
        a3 = fmaf(x[k + 3], f0w[(size_t)(k + 3) * 512 + o], a3);
    }
    float a = (a0 + a1) + (a2 + a3);
    g_h1[b * 512 + o] = a > 0.f ? a : 0.f;
}

// fc1 relu + fc2     grid (BB)
__global__ __launch_bounds__(256) void fc12_kernel(
    const float* __restrict__ f1w, const float* __restrict__ f1b,
    const float* __restrict__ f2w, const float* __restrict__ f2b,
    float* __restrict__ out)
{
    int b = blockIdx.x, tid = threadIdx.x;
    __shared__ float h1[512], h2[128];
    for (int k = tid; k < 512; k += 256) h1[k] = g_h1[b * 512 + k];
    __syncthreads();
    if (tid < 128) {
        float a0 = f1b[tid], a1 = 0.f, a2 = 0.f, a3 = 0.f;
#pragma unroll 4
        for (int k = 0; k < 512; k += 4) {
            a0 = fmaf(h1[k],     f1w[k * 128 + tid], a0);
            a1 = fmaf(h1[k + 1], f1w[(k + 1) * 128 + tid], a1);
            a2 = fmaf(h1[k + 2], f1w[(k + 2) * 128 + tid], a2);
            a3 = fmaf(h1[k + 3], f1w[(k + 3) * 128 + tid], a3);
        }
        float a = (a0 + a1) + (a2 + a3);
        h2[tid] = a > 0.f ? a : 0.f;
    }
    __syncthreads();
    if (tid < 2) {
        float a = f2b[tid];
        for (int k = 0; k < 128; k++) a = fmaf(h2[k], f2w[k * 2 + tid], a);
        out[b * 2 + tid] = a;
    }
}

extern "C" void kernel_launch(void* const* d_in, const int* in_sizes, int n_in,
                              void* d_out, int out_size) {
    const float* diff  = (const float*)d_in[0];
    const float* msg   = (const float*)d_in[1];
    const int*   mask  = (const int*)d_in[2];
    const int*   ei_d  = (const int*)d_in[3];
    const int*   ei_m  = (const int*)d_in[4];
    const float* wl    = (const float*)d_in[5];
    const float* bl    = (const float*)d_in[6];
    const float* wr    = (const float*)d_in[7];
    const float* br    = (const float*)d_in[8];
    const float* att   = (const float*)d_in[9];
    const float* gbias = (const float*)d_in[10];
    const float* wq    = (const float*)d_in[11];
    const float* bq    = (const float*)d_in[12];
    const float* wk    = (const float*)d_in[13];
    const float* wv    = (const float*)d_in[15];
    const float* bv    = (const float*)d_in[16];
    const float* wo    = (const float*)d_in[17];
    const float* bo    = (const float*)d_in[18];
    const float* lng   = (const float*)d_in[19];
    const float* lnb   = (const float*)d_in[20];
    const float* f0w   = (const float*)d_in[21];
    const float* f0b   = (const float*)d_in[22];
    const float* f1w   = (const float*)d_in[23];
    const float* f1b   = (const float*)d_in[24];
    const float* f2w   = (const float*)d_in[25];
    const float* f2b   = (const float*)d_in[26];
    float* out = (float*)d_out;

    csr_kernel<<<BB, 512>>>(ei_m);                                      // 0
    convert_a_kernel<<<BB * SS * HH / 1024, 256>>>(msg);                // 1
    convert_w_kernel<<<dim3(HH / 32, HH / 32, 2), 256>>>(wl, wr);       // 2
    gemm_bf16_kernel<<<dim3(12, (BB * SS) / BM), 256>>>(bl, br);        // 3  <- ncu
    collect0_kernel<<<BB, 256>>>(ei_d);                                 // 4
    dxl_kernel<<<dim3(3, CAPD, BB), 256>>>(diff, wl, bl);               // 5
    xr0_kernel<<<dim3(3, BB), 256>>>(diff, wr, br);                     // 6
    gat_node_kernel<<<dim3(SS, BB), 128>>>(att, gbias, msg);            // 7
    diff0_fin_kernel<<<BB, 256>>>(diff, att, gbias);                    // 8
    rq0_kernel<<<dim3(BB, NH), 256>>>(wq, bq, wk);                      // 9
    scores_kernel<<<dim3(BB, 8), 256>>>(mask);                          // 10
    softmax_kernel<<<BB * NH, 256>>>();                                 // 11
    u_kernel<<<dim3(BB, 3), 256>>>();                                   // 12
    ctx_kernel<<<dim3(3, BB), 256>>>(wv, bv);                           // 13
    fwo_kernel<<<dim3(3, BB), 256>>>(wo, bo);                           // 14
    fc0ln_kernel<<<dim3(2, BB), 256>>>(lng, lnb, f0w, f0b);             // 15
    fc12_kernel<<<BB, 256>>>(f1w, f1b, f2w, f2b, out);                  // 16
}